// round 7
// baseline (speedup 1.0000x reference)
#include <cuda_runtime.h>
#include <math.h>
#include <stdint.h>

// Problem constants (fixed shapes)
#define N_TOK 65536   // B*T
#define HDIM  512
#define NEXP  4
#define RNK   16
#define NTILES (N_TOK / 128)   // 512 token tiles of 128

// ---------------- device scratch (static; no allocations) ----------------
__device__ float g_w[N_TOK * NEXP];                  // gate weights [N,4]
__device__ float g_wz[N_TOK * NEXP * RNK];           // w*z codes    [N,64]
__device__ float g_C[NEXP * RNK * HDIM];             // fused lora_B@fc2^T
__device__ float g_xr[N_TOK * HDIM];                 // tf32, col-permuted x
__device__ float g_wr[NEXP * HDIM * HDIM];           // tf32, col-permuted fc1_w

// ===================== helpers =====================
__device__ __forceinline__ uint32_t smem_to_u32(const void* p) {
    uint32_t a;
    asm("{ .reg .u64 t; cvta.to.shared.u64 t, %1; cvt.u32.u64 %0, t; }"
        : "=r"(a) : "l"(p));
    return a;
}
__device__ __forceinline__ void cp16(uint32_t dst, const float* src) {
    asm volatile("cp.async.cg.shared.global [%0], [%1], 16;" :: "r"(dst), "l"(src));
}
__device__ __forceinline__ uint32_t tf32_rna(float v) {
    uint32_t t;
    asm("cvt.rna.tf32.f32 %0, %1;" : "=r"(t) : "f"(v));
    return t;
}
__device__ __forceinline__ void mma_tf32(float c[4], const uint32_t a[4], const uint32_t b[2]) {
    asm volatile(
        "mma.sync.aligned.m16n8k8.row.col.f32.tf32.tf32.f32 "
        "{%0,%1,%2,%3}, {%4,%5,%6,%7}, {%8,%9}, {%0,%1,%2,%3};\n"
        : "+f"(c[0]), "+f"(c[1]), "+f"(c[2]), "+f"(c[3])
        : "r"(a[0]), "r"(a[1]), "r"(a[2]), "r"(a[3]), "r"(b[0]), "r"(b[1]));
}
__device__ __forceinline__ void fma2(uint64_t& d, uint64_t a, uint64_t b) {
    asm("fma.rn.f32x2 %0, %1, %2, %3;" : "=l"(d) : "l"(a), "l"(b), "l"(d));
}
__device__ __forceinline__ uint64_t pack2(float lo, float hi) {
    uint64_t r;
    asm("mov.b64 %0, {%1, %2};" : "=l"(r) : "r"(__float_as_uint(lo)), "r"(__float_as_uint(hi)));
    return r;
}
__device__ __forceinline__ float sum2(uint64_t p) {
    uint32_t lo, hi;
    asm("mov.b64 {%0, %1}, %2;" : "=r"(lo), "=r"(hi) : "l"(p));
    return __uint_as_float(lo) + __uint_as_float(hi);
}

// =========================================================================
// Kernel 0a: fused x rounding (tf32, column-permuted) + gating.
//   One warp per token. 256 threads = 8 warps; grid N/8.
//   Permutation within each 8-col group: orig c -> (c&3)*2 + (c>>2).
// =========================================================================
__global__ void __launch_bounds__(256)
round_x_gating_kernel(const float* __restrict__ x,
                      const float* __restrict__ gate_w,
                      const float* __restrict__ thr_w) {
    const int warp = threadIdx.x >> 5, lane = threadIdx.x & 31;
    const int n = blockIdx.x * 8 + warp;
    const float* xr = x + (size_t)n * HDIM;
    float* xo = g_xr + (size_t)n * HDIM;

    float a0 = 0.f, a1 = 0.f, a2 = 0.f, a3 = 0.f, at = 0.f;
#pragma unroll
    for (int it = 0; it < 4; it++) {
        const int k0 = it * 128 + lane * 4;
        float4 v = *(const float4*)&xr[k0];
        // gate dots (fp32, original values)
        float4 w0 = *(const float4*)&gate_w[0 * HDIM + k0];
        float4 w1 = *(const float4*)&gate_w[1 * HDIM + k0];
        float4 w2 = *(const float4*)&gate_w[2 * HDIM + k0];
        float4 w3 = *(const float4*)&gate_w[3 * HDIM + k0];
        float4 wt = *(const float4*)&thr_w[k0];
        a0 += v.x * w0.x + v.y * w0.y + v.z * w0.z + v.w * w0.w;
        a1 += v.x * w1.x + v.y * w1.y + v.z * w1.z + v.w * w1.w;
        a2 += v.x * w2.x + v.y * w2.y + v.z * w2.z + v.w * w2.w;
        a3 += v.x * w3.x + v.y * w3.y + v.z * w3.z + v.w * w3.w;
        at += v.x * wt.x + v.y * wt.y + v.z * wt.z + v.w * wt.w;
        // permuted tf32 store
        const int base = k0 & ~7;
        const int odd = (k0 >> 2) & 1;
        ((uint32_t*)xo)[base + 0 + odd] = tf32_rna(v.x);
        ((uint32_t*)xo)[base + 2 + odd] = tf32_rna(v.y);
        ((uint32_t*)xo)[base + 4 + odd] = tf32_rna(v.z);
        ((uint32_t*)xo)[base + 6 + odd] = tf32_rna(v.w);
    }
#pragma unroll
    for (int off = 16; off > 0; off >>= 1) {
        a0 += __shfl_xor_sync(0xffffffffu, a0, off);
        a1 += __shfl_xor_sync(0xffffffffu, a1, off);
        a2 += __shfl_xor_sync(0xffffffffu, a2, off);
        a3 += __shfl_xor_sync(0xffffffffu, a3, off);
        at += __shfl_xor_sync(0xffffffffu, at, off);
    }
    if (lane == 0) {
        float m = fmaxf(fmaxf(a0, a1), fmaxf(a2, a3));
        float e0 = expf(a0 - m), e1 = expf(a1 - m), e2 = expf(a2 - m), e3 = expf(a3 - m);
        float inv_s = 1.f / (e0 + e1 + e2 + e3);
        float thr = (1.f / (1.f + expf(-at))) * 0.25f;
        float w0 = e0 * inv_s - thr, w1 = e1 * inv_s - thr;
        float w2 = e2 * inv_s - thr, w3 = e3 * inv_s - thr;
        w0 = (w0 >= 0.f) ? w0 : 0.f;  w1 = (w1 >= 0.f) ? w1 : 0.f;
        w2 = (w2 >= 0.f) ? w2 : 0.f;  w3 = (w3 >= 0.f) ? w3 : 0.f;
        float ws = w0 + w1 + w2 + w3;
        if (ws == 0.f) ws = 1.f;
        float inv = 1.f / ws;
        g_w[n * 4 + 0] = w0 * inv;  g_w[n * 4 + 1] = w1 * inv;
        g_w[n * 4 + 2] = w2 * inv;  g_w[n * 4 + 3] = w3 * inv;
    }
}

// =========================================================================
// Kernel 0b: round fc1_w to tf32, column-permuted.
// =========================================================================
__global__ void round_w_kernel(const float4* __restrict__ src) {
    int i = blockIdx.x * blockDim.x + threadIdx.x;   // float4 index
    float4 v = src[i];
    const int k = (i * 4) & (HDIM - 1);
    const size_t rowbase = (size_t)(i * 4 - k);
    const int base = k & ~7;
    const int odd = (k >> 2) & 1;
    uint32_t* dst = (uint32_t*)g_wr + rowbase;
    dst[base + 0 + odd] = tf32_rna(v.x);
    dst[base + 2 + odd] = tf32_rna(v.y);
    dst[base + 4 + odd] = tf32_rna(v.z);
    dst[base + 6 + odd] = tf32_rna(v.w);
}

// =========================================================================
// Kernel 1: C[e][r][d] = sum_o lora_B[e][r][o] * fc2_w[e][d][o]
// =========================================================================
__global__ void precompute_C_kernel(const float* __restrict__ lora_B,
                                    const float* __restrict__ fc2_w) {
    const int e = blockIdx.x;
    const int dbase = blockIdx.y * 64;
    __shared__ float lbs[RNK * HDIM];
    for (int i = threadIdx.x; i < RNK * HDIM; i += blockDim.x)
        lbs[i] = lora_B[(size_t)e * RNK * HDIM + i];
    __syncthreads();

    const int warp = threadIdx.x >> 5, lane = threadIdx.x & 31;
    for (int dd = 0; dd < 8; dd++) {
        const int d = dbase + warp * 8 + dd;
        float acc[RNK];
#pragma unroll
        for (int r = 0; r < RNK; r++) acc[r] = 0.f;
        const float* fr = fc2_w + ((size_t)e * HDIM + d) * HDIM;
        for (int o = lane; o < HDIM; o += 32) {
            float fv = fr[o];
#pragma unroll
            for (int r = 0; r < RNK; r++) acc[r] += fv * lbs[r * HDIM + o];
        }
#pragma unroll
        for (int r = 0; r < RNK; r++) {
#pragma unroll
            for (int off = 16; off > 0; off >>= 1)
                acc[r] += __shfl_xor_sync(0xffffffffu, acc[r], off);
        }
        if (lane == 0) {
#pragma unroll
            for (int r = 0; r < RNK; r++)
                g_C[(size_t)(e * RNK + r) * HDIM + d] = acc[r];
        }
    }
}

// =========================================================================
// Kernel 3: mma.sync tf32 expert kernel.
//   Block = (expert e, 128-token tile). 512 threads = 16 warps (2m x 8n),
//   warp tile 64x32, loops 2 n-chunks of 256. K=512 in 16 chunks of 32.
//   3-stage cp.async pipeline, ONE barrier per k-iter. Fragments loaded as
//   LDS.64 thanks to column permutation. Row stride = 40 words (conflict-free).
// =========================================================================
#define EX_STRIDE 40                       // words per smem row
#define EX_ST_BYTES 61440                  // (128 + 256) * 40 * 4
#define EX_A(s)   ((s) * EX_ST_BYTES)
#define EX_B(s)   ((s) * EX_ST_BYTES + 20480)
#define EX_HS     0                        // [128][260] f32, aliases pipeline
#define EX_AST    184320                   // [16][260] f32
#define SMEM_EXP  (184320 + 16640)         // 200960 B

__device__ __forceinline__ void ex_load_tile(uint32_t smem_base, int kt, int s, int n0,
                                             const float* __restrict__ Xe,
                                             const float* __restrict__ We, int tid) {
    const uint32_t abase = smem_base + EX_A(s);
    const uint32_t bbase = smem_base + EX_B(s);
    const int koff = kt * 32;
#pragma unroll
    for (int it = 0; it < 6; it++) {
        int idx = tid + it * 512;
        if (idx < 1024) {                 // A: 128 rows x 8 x 16B
            int row = idx >> 3, c = idx & 7;
            cp16(abase + row * 160 + c * 16, Xe + (size_t)row * HDIM + koff + c * 4);
        } else {                          // B: 256 rows x 8 x 16B
            int i = idx - 1024;
            int row = i >> 3, c = i & 7;
            cp16(bbase + row * 160 + c * 16,
                 We + (size_t)(n0 + row) * HDIM + koff + c * 4);
        }
    }
}

__global__ void __launch_bounds__(512, 1)
expert_mma_kernel(const float* __restrict__ lora_A) {
    const int e    = blockIdx.x;
    const int tile = blockIdx.y;
    const int m0   = tile * 128;
    const int tid  = threadIdx.x;
    const int warp = tid >> 5, lane = tid & 31;
    const int g = lane >> 2, tg = lane & 3;
    const int warp_m = warp >> 3, warp_n = warp & 7;   // 2 x 8

    extern __shared__ char smem[];
    const uint32_t smem_base = smem_to_u32(smem);
    float* Hs  = (float*)(smem + EX_HS);    // [128][260]
    float* Ast = (float*)(smem + EX_AST);   // [16][260]

    const float* Xe = g_xr + (size_t)m0 * HDIM;
    const float* We = g_wr + (size_t)e * HDIM * HDIM;
    const float* Ae = lora_A + (size_t)e * HDIM * RNK;

    const int zr = tid & 15;
    const int zrowb = tid >> 4;     // 0..31
    uint64_t zp[4][2];              // packed z accumulators (pairwise)
#pragma unroll
    for (int q = 0; q < 4; q++) { zp[q][0] = 0ull; zp[q][1] = 0ull; }

    for (int nc = 0; nc < 2; nc++) {
        const int n0 = nc * 256;
        __syncthreads();   // prev Hs/Ast fully consumed; pipeline region free

        ex_load_tile(smem_base, 0, 0, n0, Xe, We, tid);
        asm volatile("cp.async.commit_group;" ::: "memory");
        ex_load_tile(smem_base, 1, 1, n0, Xe, We, tid);
        asm volatile("cp.async.commit_group;" ::: "memory");

        // stage lora_A chunk transposed: Ast[r][c] = A[n0+c][r]
        for (int idx = tid; idx < 256 * RNK; idx += 512) {
            int r = idx >> 8, c = idx & 255;
            Ast[r * 260 + c] = Ae[(size_t)(n0 + c) * RNK + r];
        }

        float acc[4][4][4];
#pragma unroll
        for (int mi = 0; mi < 4; mi++)
#pragma unroll
            for (int ni = 0; ni < 4; ni++)
#pragma unroll
                for (int c = 0; c < 4; c++) acc[mi][ni][c] = 0.f;

        for (int kc = 0; kc < 16; kc++) {
            const int s = kc % 3;
            if (kc < 15) asm volatile("cp.async.wait_group 1;" ::: "memory");
            else         asm volatile("cp.async.wait_group 0;" ::: "memory");
            __syncthreads();   // tile kc visible to all; stage (kc-1)%3 free for reuse

            if (kc + 2 < 16) {
                ex_load_tile(smem_base, kc + 2, (kc + 2) % 3, n0, Xe, We, tid);
                asm volatile("cp.async.commit_group;" ::: "memory");
            }

            const uint32_t* Xs = (const uint32_t*)(smem + EX_A(s));
            const uint32_t* Ws = (const uint32_t*)(smem + EX_B(s));
#pragma unroll
            for (int st = 0; st < 4; st++) {
                const int kk = st * 8;
                uint32_t a[4][4], b[4][2];
#pragma unroll
                for (int mi = 0; mi < 4; mi++) {
                    const int row = warp_m * 64 + mi * 16 + g;
                    uint2 lo = *(const uint2*)&Xs[row * EX_STRIDE + kk + 2 * tg];
                    uint2 hi = *(const uint2*)&Xs[(row + 8) * EX_STRIDE + kk + 2 * tg];
                    a[mi][0] = lo.x; a[mi][1] = hi.x; a[mi][2] = lo.y; a[mi][3] = hi.y;
                }
#pragma unroll
                for (int ni = 0; ni < 4; ni++) {
                    const int col = warp_n * 32 + ni * 8 + g;
                    uint2 bb = *(const uint2*)&Ws[col * EX_STRIDE + kk + 2 * tg];
                    b[ni][0] = bb.x; b[ni][1] = bb.y;
                }
#pragma unroll
                for (int mi = 0; mi < 4; mi++)
#pragma unroll
                    for (int ni = 0; ni < 4; ni++)
                        mma_tf32(acc[mi][ni], a[mi], b[ni]);
            }
        }

        __syncthreads();   // all MMA reads of pipeline region done -> Hs may alias
        // stage relu(H) -> Hs
#pragma unroll
        for (int mi = 0; mi < 4; mi++)
#pragma unroll
            for (int ni = 0; ni < 4; ni++) {
                const int row = warp_m * 64 + mi * 16 + g;
                const int col = warp_n * 32 + ni * 8 + 2 * tg;
                Hs[row * 260 + col]           = fmaxf(acc[mi][ni][0], 0.f);
                Hs[row * 260 + col + 1]       = fmaxf(acc[mi][ni][1], 0.f);
                Hs[(row + 8) * 260 + col]     = fmaxf(acc[mi][ni][2], 0.f);
                Hs[(row + 8) * 260 + col + 1] = fmaxf(acc[mi][ni][3], 0.f);
            }
        __syncthreads();

        // rank-16 projection with f32x2: zp[q] += H[rowb+32q][:] . Ast[zr][:]
#pragma unroll
        for (int c4 = 0; c4 < 64; c4++) {
            float4 av = *(const float4*)&Ast[zr * 260 + c4 * 4];
            uint64_t a01 = pack2(av.x, av.y);
            uint64_t a23 = pack2(av.z, av.w);
#pragma unroll
            for (int q = 0; q < 4; q++) {
                float4 hv = *(const float4*)&Hs[(zrowb + 32 * q) * 260 + c4 * 4];
                fma2(zp[q][0], pack2(hv.x, hv.y), a01);
                fma2(zp[q][1], pack2(hv.z, hv.w), a23);
            }
        }
    }

    // write w*z
#pragma unroll
    for (int q = 0; q < 4; q++) {
        const int n = m0 + zrowb + 32 * q;
        const float w = g_w[n * 4 + e];
        g_wz[(size_t)n * (NEXP * RNK) + e * RNK + zr] =
            w * (sum2(zp[q][0]) + sum2(zp[q][1]));
    }
}

// =========================================================================
// Kernel 4: combine. out[n][dbase+d] = sum_j wz[n][j] * C[j][dbase+d]
// Grid (1024 token-tiles, 2 d-halves); 2 blocks/SM; f32x2 inner loop.
// =========================================================================
#define SMEM_COMBINE ((64 * 256 + 64 * 68) * 4)

__global__ void __launch_bounds__(256, 2)
combine_kernel(float* __restrict__ out) {
    extern __shared__ float csmem[];
    float* Cs = csmem;               // [64][256]
    float* Zs = Cs + 64 * 256;       // [64][68]

    const int tile = blockIdx.x;
    const int dbase = blockIdx.y * 256;
    const int tid = threadIdx.x;

    for (int i = tid; i < 64 * 64; i += 256) {     // [64][256] as float4
        int j = i >> 6, c4 = i & 63;
        ((float4*)Cs)[i] = *(const float4*)&g_C[(size_t)j * HDIM + dbase + c4 * 4];
    }
    const float* wz = g_wz + (size_t)tile * 64 * 64;
    for (int i = tid; i < 64 * 64; i += 256) {
        int row = i >> 6, j = i & 63;
        Zs[row * 68 + j] = wz[i];
    }
    __syncthreads();

    const int warp = tid >> 5, lane = tid & 31;
    const int rowbase = warp * 8;
    float* outt = out + (size_t)tile * 64 * HDIM + dbase;

    for (int rg = 0; rg < 2; rg++) {
        uint64_t acc[4][4];
#pragma unroll
        for (int rr = 0; rr < 4; rr++)
#pragma unroll
            for (int i = 0; i < 4; i++) acc[rr][i] = 0ull;

        for (int j = 0; j < 64; j++) {
            const uint64_t* c0 = (const uint64_t*)&Cs[j * 256 + lane * 4];
            const uint64_t* c1 = (const uint64_t*)&Cs[j * 256 + 128 + lane * 4];
            uint64_t p0 = c0[0], p1 = c0[1], p2 = c1[0], p3 = c1[1];
#pragma unroll
            for (int rr = 0; rr < 4; rr++) {
                const float zv = Zs[(rowbase + rg * 4 + rr) * 68 + j];
                uint64_t zz = pack2(zv, zv);
                fma2(acc[rr][0], zz, p0);
                fma2(acc[rr][1], zz, p1);
                fma2(acc[rr][2], zz, p2);
                fma2(acc[rr][3], zz, p3);
            }
        }
#pragma unroll
        for (int rr = 0; rr < 4; rr++) {
            const int row = rowbase + rg * 4 + rr;
            uint64_t* o0 = (uint64_t*)&outt[(size_t)row * HDIM + lane * 4];
            uint64_t* o1 = (uint64_t*)&outt[(size_t)row * HDIM + 128 + lane * 4];
            o0[0] = acc[rr][0];  o0[1] = acc[rr][1];
            o1[0] = acc[rr][2];  o1[1] = acc[rr][3];
        }
    }
}

// =========================================================================
extern "C" void kernel_launch(void* const* d_in, const int* in_sizes, int n_in,
                              void* d_out, int out_size) {
    const float* x      = (const float*)d_in[0];
    const float* gate_w = (const float*)d_in[1];
    const float* thr_w  = (const float*)d_in[2];
    const float* fc1_w  = (const float*)d_in[3];
    const float* lora_A = (const float*)d_in[4];
    const float* lora_B = (const float*)d_in[5];
    const float* fc2_w  = (const float*)d_in[6];
    float* out = (float*)d_out;

    cudaFuncSetAttribute(expert_mma_kernel,
                         cudaFuncAttributeMaxDynamicSharedMemorySize, SMEM_EXP);
    cudaFuncSetAttribute(combine_kernel,
                         cudaFuncAttributeMaxDynamicSharedMemorySize, SMEM_COMBINE);

    round_x_gating_kernel<<<N_TOK / 8, 256>>>(x, gate_w, thr_w);
    round_w_kernel<<<(NEXP * HDIM * HDIM / 4) / 256, 256>>>((const float4*)fc1_w);
    precompute_C_kernel<<<dim3(NEXP, HDIM / 64), 256>>>(lora_B, fc2_w);
    expert_mma_kernel<<<dim3(NEXP, NTILES), 512, SMEM_EXP>>>(lora_A);
    combine_kernel<<<dim3(N_TOK / 64, 2), 256, SMEM_COMBINE>>>(out);
}

// round 8
// speedup vs baseline: 1.5082x; 1.5082x over previous
#include <cuda_runtime.h>
#include <math.h>
#include <stdint.h>

// Problem constants (fixed shapes)
#define N_TOK 65536   // B*T
#define HDIM  512
#define NEXP  4
#define RNK   16
#define NTILES (N_TOK / 128)   // 512 token tiles of 128

// ---------------- device scratch (static; no allocations) ----------------
__device__ float g_w[N_TOK * NEXP];                  // gate weights [N,4]
__device__ float g_wz[N_TOK * NEXP * RNK];           // w*z codes    [N,64]
__device__ float g_C[NEXP * RNK * HDIM];             // fused lora_B@fc2^T
__device__ float g_xr[N_TOK * HDIM];                 // tf32, col-permuted x
__device__ float g_wr[NEXP * HDIM * HDIM];           // tf32, col-permuted fc1_w

// ===================== helpers =====================
__device__ __forceinline__ uint32_t smem_to_u32(const void* p) {
    uint32_t a;
    asm("{ .reg .u64 t; cvta.to.shared.u64 t, %1; cvt.u32.u64 %0, t; }"
        : "=r"(a) : "l"(p));
    return a;
}
__device__ __forceinline__ void cp16(uint32_t dst, const float* src) {
    asm volatile("cp.async.cg.shared.global [%0], [%1], 16;" :: "r"(dst), "l"(src));
}
__device__ __forceinline__ uint32_t tf32_rna(float v) {
    uint32_t t;
    asm("cvt.rna.tf32.f32 %0, %1;" : "=r"(t) : "f"(v));
    return t;
}
__device__ __forceinline__ void mma_tf32(float c[4], const uint32_t a[4], const uint32_t b[2]) {
    asm volatile(
        "mma.sync.aligned.m16n8k8.row.col.f32.tf32.tf32.f32 "
        "{%0,%1,%2,%3}, {%4,%5,%6,%7}, {%8,%9}, {%0,%1,%2,%3};\n"
        : "+f"(c[0]), "+f"(c[1]), "+f"(c[2]), "+f"(c[3])
        : "r"(a[0]), "r"(a[1]), "r"(a[2]), "r"(a[3]), "r"(b[0]), "r"(b[1]));
}
__device__ __forceinline__ void fma2(uint64_t& d, uint64_t a, uint64_t b) {
    asm("fma.rn.f32x2 %0, %1, %2, %3;" : "=l"(d) : "l"(a), "l"(b), "l"(d));
}
__device__ __forceinline__ uint64_t pack2(float lo, float hi) {
    uint64_t r;
    asm("mov.b64 %0, {%1, %2};" : "=l"(r) : "r"(__float_as_uint(lo)), "r"(__float_as_uint(hi)));
    return r;
}

// =========================================================================
// Kernel 0a: fused x rounding (tf32, column-permuted) + gating.
//   One warp per token. Permutation in each 8-col group: c -> (c&3)*2+(c>>2).
//   Each lane's 4 stores land in its own 32B sector -> no write amplification.
// =========================================================================
__global__ void __launch_bounds__(256)
round_x_gating_kernel(const float* __restrict__ x,
                      const float* __restrict__ gate_w,
                      const float* __restrict__ thr_w) {
    const int warp = threadIdx.x >> 5, lane = threadIdx.x & 31;
    const int n = blockIdx.x * 8 + warp;
    const float* xr = x + (size_t)n * HDIM;
    float* xo = g_xr + (size_t)n * HDIM;

    float a0 = 0.f, a1 = 0.f, a2 = 0.f, a3 = 0.f, at = 0.f;
#pragma unroll
    for (int it = 0; it < 4; it++) {
        const int k0 = it * 128 + lane * 4;
        float4 v = *(const float4*)&xr[k0];
        float4 w0 = *(const float4*)&gate_w[0 * HDIM + k0];
        float4 w1 = *(const float4*)&gate_w[1 * HDIM + k0];
        float4 w2 = *(const float4*)&gate_w[2 * HDIM + k0];
        float4 w3 = *(const float4*)&gate_w[3 * HDIM + k0];
        float4 wt = *(const float4*)&thr_w[k0];
        a0 += v.x * w0.x + v.y * w0.y + v.z * w0.z + v.w * w0.w;
        a1 += v.x * w1.x + v.y * w1.y + v.z * w1.z + v.w * w1.w;
        a2 += v.x * w2.x + v.y * w2.y + v.z * w2.z + v.w * w2.w;
        a3 += v.x * w3.x + v.y * w3.y + v.z * w3.z + v.w * w3.w;
        at += v.x * wt.x + v.y * wt.y + v.z * wt.z + v.w * wt.w;
        const int base = k0 & ~7;
        const int odd = (k0 >> 2) & 1;
        ((uint32_t*)xo)[base + 0 + odd] = tf32_rna(v.x);
        ((uint32_t*)xo)[base + 2 + odd] = tf32_rna(v.y);
        ((uint32_t*)xo)[base + 4 + odd] = tf32_rna(v.z);
        ((uint32_t*)xo)[base + 6 + odd] = tf32_rna(v.w);
    }
#pragma unroll
    for (int off = 16; off > 0; off >>= 1) {
        a0 += __shfl_xor_sync(0xffffffffu, a0, off);
        a1 += __shfl_xor_sync(0xffffffffu, a1, off);
        a2 += __shfl_xor_sync(0xffffffffu, a2, off);
        a3 += __shfl_xor_sync(0xffffffffu, a3, off);
        at += __shfl_xor_sync(0xffffffffu, at, off);
    }
    if (lane == 0) {
        float m = fmaxf(fmaxf(a0, a1), fmaxf(a2, a3));
        float e0 = expf(a0 - m), e1 = expf(a1 - m), e2 = expf(a2 - m), e3 = expf(a3 - m);
        float inv_s = 1.f / (e0 + e1 + e2 + e3);
        float thr = (1.f / (1.f + expf(-at))) * 0.25f;
        float w0 = e0 * inv_s - thr, w1 = e1 * inv_s - thr;
        float w2 = e2 * inv_s - thr, w3 = e3 * inv_s - thr;
        w0 = (w0 >= 0.f) ? w0 : 0.f;  w1 = (w1 >= 0.f) ? w1 : 0.f;
        w2 = (w2 >= 0.f) ? w2 : 0.f;  w3 = (w3 >= 0.f) ? w3 : 0.f;
        float ws = w0 + w1 + w2 + w3;
        if (ws == 0.f) ws = 1.f;
        float inv = 1.f / ws;
        g_w[n * 4 + 0] = w0 * inv;  g_w[n * 4 + 1] = w1 * inv;
        g_w[n * 4 + 2] = w2 * inv;  g_w[n * 4 + 3] = w3 * inv;
    }
}

// =========================================================================
// Kernel 0b: round fc1_w to tf32, column-permuted.
// =========================================================================
__global__ void round_w_kernel(const float4* __restrict__ src) {
    int i = blockIdx.x * blockDim.x + threadIdx.x;   // float4 index
    float4 v = src[i];
    const int k = (i * 4) & (HDIM - 1);
    const size_t rowbase = (size_t)(i * 4 - k);
    const int base = k & ~7;
    const int odd = (k >> 2) & 1;
    uint32_t* dst = (uint32_t*)g_wr + rowbase;
    dst[base + 0 + odd] = tf32_rna(v.x);
    dst[base + 2 + odd] = tf32_rna(v.y);
    dst[base + 4 + odd] = tf32_rna(v.z);
    dst[base + 6 + odd] = tf32_rna(v.w);
}

// =========================================================================
// Kernel 1: C[e][r][d] = sum_o lora_B[e][r][o] * fc2_w[e][d][o]
// =========================================================================
__global__ void precompute_C_kernel(const float* __restrict__ lora_B,
                                    const float* __restrict__ fc2_w) {
    const int e = blockIdx.x;
    const int dbase = blockIdx.y * 64;
    __shared__ float lbs[RNK * HDIM];
    for (int i = threadIdx.x; i < RNK * HDIM; i += blockDim.x)
        lbs[i] = lora_B[(size_t)e * RNK * HDIM + i];
    __syncthreads();

    const int warp = threadIdx.x >> 5, lane = threadIdx.x & 31;
    for (int dd = 0; dd < 8; dd++) {
        const int d = dbase + warp * 8 + dd;
        float acc[RNK];
#pragma unroll
        for (int r = 0; r < RNK; r++) acc[r] = 0.f;
        const float* fr = fc2_w + ((size_t)e * HDIM + d) * HDIM;
        for (int o = lane; o < HDIM; o += 32) {
            float fv = fr[o];
#pragma unroll
            for (int r = 0; r < RNK; r++) acc[r] += fv * lbs[r * HDIM + o];
        }
#pragma unroll
        for (int r = 0; r < RNK; r++) {
#pragma unroll
            for (int off = 16; off > 0; off >>= 1)
                acc[r] += __shfl_xor_sync(0xffffffffu, acc[r], off);
        }
        if (lane == 0) {
#pragma unroll
            for (int r = 0; r < RNK; r++)
                g_C[(size_t)(e * RNK + r) * HDIM + d] = acc[r];
        }
    }
}

// =========================================================================
// Kernel 3: mma.sync tf32 expert kernel.
//   Block = (expert e, 128-token tile). 512 threads = 16 warps (2m x 8n),
//   warp tile 64x32, loops 2 n-chunks of 256. K=512 in 16 chunks of 32.
//   3-stage cp.async pipeline, ONE barrier per k-iter. LDS.64 fragment loads
//   via column permutation. Epilogue: SCALAR z accumulators (reg budget!).
// =========================================================================
#define EX_STRIDE 40                       // words per smem row
#define EX_ST_BYTES 61440                  // (128 + 256) * 40 * 4
#define EX_A(s)   ((s) * EX_ST_BYTES)
#define EX_B(s)   ((s) * EX_ST_BYTES + 20480)
#define EX_HS     0                        // [128][260] f32, aliases pipeline
#define EX_AST    184320                   // [16][260] f32
#define SMEM_EXP  (184320 + 16640)         // 200960 B

__device__ __forceinline__ void ex_load_tile(uint32_t smem_base, int kt, int s, int n0,
                                             const float* __restrict__ Xe,
                                             const float* __restrict__ We, int tid) {
    const uint32_t abase = smem_base + EX_A(s);
    const uint32_t bbase = smem_base + EX_B(s);
    const int koff = kt * 32;
#pragma unroll
    for (int it = 0; it < 6; it++) {
        int idx = tid + it * 512;
        if (idx < 1024) {                 // A: 128 rows x 8 x 16B
            int row = idx >> 3, c = idx & 7;
            cp16(abase + row * 160 + c * 16, Xe + (size_t)row * HDIM + koff + c * 4);
        } else {                          // B: 256 rows x 8 x 16B
            int i = idx - 1024;
            int row = i >> 3, c = i & 7;
            cp16(bbase + row * 160 + c * 16,
                 We + (size_t)(n0 + row) * HDIM + koff + c * 4);
        }
    }
}

__global__ void __launch_bounds__(512, 1)
expert_mma_kernel(const float* __restrict__ lora_A) {
    const int e    = blockIdx.x;
    const int tile = blockIdx.y;
    const int m0   = tile * 128;
    const int tid  = threadIdx.x;
    const int warp = tid >> 5, lane = tid & 31;
    const int g = lane >> 2, tg = lane & 3;
    const int warp_m = warp >> 3, warp_n = warp & 7;   // 2 x 8

    extern __shared__ char smem[];
    const uint32_t smem_base = smem_to_u32(smem);
    float* Hs  = (float*)(smem + EX_HS);    // [128][260]
    float* Ast = (float*)(smem + EX_AST);   // [16][260]

    const float* Xe = g_xr + (size_t)m0 * HDIM;
    const float* We = g_wr + (size_t)e * HDIM * HDIM;
    const float* Ae = lora_A + (size_t)e * HDIM * RNK;

    const int zr = tid & 15;
    const int zrowb = tid >> 4;     // 0..31
    float zacc[4] = {0.f, 0.f, 0.f, 0.f};   // scalar accumulators (no spill)

    for (int nc = 0; nc < 2; nc++) {
        const int n0 = nc * 256;
        __syncthreads();   // prev Hs/Ast fully consumed; pipeline region free

        ex_load_tile(smem_base, 0, 0, n0, Xe, We, tid);
        asm volatile("cp.async.commit_group;" ::: "memory");
        ex_load_tile(smem_base, 1, 1, n0, Xe, We, tid);
        asm volatile("cp.async.commit_group;" ::: "memory");

        // stage lora_A chunk transposed: Ast[r][c] = A[n0+c][r]
        for (int idx = tid; idx < 256 * RNK; idx += 512) {
            int r = idx >> 8, c = idx & 255;
            Ast[r * 260 + c] = Ae[(size_t)(n0 + c) * RNK + r];
        }

        float acc[4][4][4];
#pragma unroll
        for (int mi = 0; mi < 4; mi++)
#pragma unroll
            for (int ni = 0; ni < 4; ni++)
#pragma unroll
                for (int c = 0; c < 4; c++) acc[mi][ni][c] = 0.f;

        for (int kc = 0; kc < 16; kc++) {
            const int s = kc % 3;
            if (kc < 15) asm volatile("cp.async.wait_group 1;" ::: "memory");
            else         asm volatile("cp.async.wait_group 0;" ::: "memory");
            __syncthreads();   // tile kc visible; stage (kc+2)%3 free for reuse

            if (kc + 2 < 16) {
                ex_load_tile(smem_base, kc + 2, (kc + 2) % 3, n0, Xe, We, tid);
                asm volatile("cp.async.commit_group;" ::: "memory");
            }

            const uint32_t* Xs = (const uint32_t*)(smem + EX_A(s));
            const uint32_t* Ws = (const uint32_t*)(smem + EX_B(s));
#pragma unroll
            for (int st = 0; st < 4; st++) {
                const int kk = st * 8;
                uint32_t a[4][4], b[4][2];
#pragma unroll
                for (int mi = 0; mi < 4; mi++) {
                    const int row = warp_m * 64 + mi * 16 + g;
                    uint2 lo = *(const uint2*)&Xs[row * EX_STRIDE + kk + 2 * tg];
                    uint2 hi = *(const uint2*)&Xs[(row + 8) * EX_STRIDE + kk + 2 * tg];
                    a[mi][0] = lo.x; a[mi][1] = hi.x; a[mi][2] = lo.y; a[mi][3] = hi.y;
                }
#pragma unroll
                for (int ni = 0; ni < 4; ni++) {
                    const int col = warp_n * 32 + ni * 8 + g;
                    uint2 bb = *(const uint2*)&Ws[col * EX_STRIDE + kk + 2 * tg];
                    b[ni][0] = bb.x; b[ni][1] = bb.y;
                }
#pragma unroll
                for (int mi = 0; mi < 4; mi++)
#pragma unroll
                    for (int ni = 0; ni < 4; ni++)
                        mma_tf32(acc[mi][ni], a[mi], b[ni]);
            }
        }

        __syncthreads();   // all MMA reads of pipeline region done -> Hs may alias
        // stage relu(H) -> Hs
#pragma unroll
        for (int mi = 0; mi < 4; mi++)
#pragma unroll
            for (int ni = 0; ni < 4; ni++) {
                const int row = warp_m * 64 + mi * 16 + g;
                const int col = warp_n * 32 + ni * 8 + 2 * tg;
                Hs[row * 260 + col]           = fmaxf(acc[mi][ni][0], 0.f);
                Hs[row * 260 + col + 1]       = fmaxf(acc[mi][ni][1], 0.f);
                Hs[(row + 8) * 260 + col]     = fmaxf(acc[mi][ni][2], 0.f);
                Hs[(row + 8) * 260 + col + 1] = fmaxf(acc[mi][ni][3], 0.f);
            }
        __syncthreads();

        // rank-16 projection: zacc[q] += Hs[rowb+32q][:] . Ast[zr][:]
#pragma unroll
        for (int c4 = 0; c4 < 64; c4++) {
            float4 av = *(const float4*)&Ast[zr * 260 + c4 * 4];
#pragma unroll
            for (int q = 0; q < 4; q++) {
                float4 hv = *(const float4*)&Hs[(zrowb + 32 * q) * 260 + c4 * 4];
                zacc[q] += hv.x * av.x + hv.y * av.y + hv.z * av.z + hv.w * av.w;
            }
        }
    }

    // write w*z
#pragma unroll
    for (int q = 0; q < 4; q++) {
        const int n = m0 + zrowb + 32 * q;
        const float w = g_w[n * 4 + e];
        g_wz[(size_t)n * (NEXP * RNK) + e * RNK + zr] = w * zacc[q];
    }
}

// =========================================================================
// Kernel 4: combine. out[n][dbase+d] = sum_j wz[n][j] * C[j][dbase+d]
// Grid (1024 token-tiles, 2 d-halves); 2 blocks/SM; f32x2 inner loop.
// =========================================================================
#define SMEM_COMBINE ((64 * 256 + 64 * 68) * 4)

__global__ void __launch_bounds__(256, 2)
combine_kernel(float* __restrict__ out) {
    extern __shared__ float csmem[];
    float* Cs = csmem;               // [64][256]
    float* Zs = Cs + 64 * 256;       // [64][68]

    const int tile = blockIdx.x;
    const int dbase = blockIdx.y * 256;
    const int tid = threadIdx.x;

    for (int i = tid; i < 64 * 64; i += 256) {     // [64][256] as float4
        int j = i >> 6, c4 = i & 63;
        ((float4*)Cs)[i] = *(const float4*)&g_C[(size_t)j * HDIM + dbase + c4 * 4];
    }
    const float* wz = g_wz + (size_t)tile * 64 * 64;
    for (int i = tid; i < 64 * 64; i += 256) {
        int row = i >> 6, j = i & 63;
        Zs[row * 68 + j] = wz[i];
    }
    __syncthreads();

    const int warp = tid >> 5, lane = tid & 31;
    const int rowbase = warp * 8;
    float* outt = out + (size_t)tile * 64 * HDIM + dbase;

    for (int rg = 0; rg < 2; rg++) {
        uint64_t acc[4][4];
#pragma unroll
        for (int rr = 0; rr < 4; rr++)
#pragma unroll
            for (int i = 0; i < 4; i++) acc[rr][i] = 0ull;

        for (int j = 0; j < 64; j++) {
            const uint64_t* c0 = (const uint64_t*)&Cs[j * 256 + lane * 4];
            const uint64_t* c1 = (const uint64_t*)&Cs[j * 256 + 128 + lane * 4];
            uint64_t p0 = c0[0], p1 = c0[1], p2 = c1[0], p3 = c1[1];
#pragma unroll
            for (int rr = 0; rr < 4; rr++) {
                const float zv = Zs[(rowbase + rg * 4 + rr) * 68 + j];
                uint64_t zz = pack2(zv, zv);
                fma2(acc[rr][0], zz, p0);
                fma2(acc[rr][1], zz, p1);
                fma2(acc[rr][2], zz, p2);
                fma2(acc[rr][3], zz, p3);
            }
        }
#pragma unroll
        for (int rr = 0; rr < 4; rr++) {
            const int row = rowbase + rg * 4 + rr;
            uint64_t* o0 = (uint64_t*)&outt[(size_t)row * HDIM + lane * 4];
            uint64_t* o1 = (uint64_t*)&outt[(size_t)row * HDIM + 128 + lane * 4];
            o0[0] = acc[rr][0];  o0[1] = acc[rr][1];
            o1[0] = acc[rr][2];  o1[1] = acc[rr][3];
        }
    }
}

// =========================================================================
extern "C" void kernel_launch(void* const* d_in, const int* in_sizes, int n_in,
                              void* d_out, int out_size) {
    const float* x      = (const float*)d_in[0];
    const float* gate_w = (const float*)d_in[1];
    const float* thr_w  = (const float*)d_in[2];
    const float* fc1_w  = (const float*)d_in[3];
    const float* lora_A = (const float*)d_in[4];
    const float* lora_B = (const float*)d_in[5];
    const float* fc2_w  = (const float*)d_in[6];
    float* out = (float*)d_out;

    cudaFuncSetAttribute(expert_mma_kernel,
                         cudaFuncAttributeMaxDynamicSharedMemorySize, SMEM_EXP);
    cudaFuncSetAttribute(combine_kernel,
                         cudaFuncAttributeMaxDynamicSharedMemorySize, SMEM_COMBINE);

    round_x_gating_kernel<<<N_TOK / 8, 256>>>(x, gate_w, thr_w);
    round_w_kernel<<<(NEXP * HDIM * HDIM / 4) / 256, 256>>>((const float4*)fc1_w);
    precompute_C_kernel<<<dim3(NEXP, HDIM / 64), 256>>>(lora_B, fc2_w);
    expert_mma_kernel<<<dim3(NEXP, NTILES), 512, SMEM_EXP>>>(lora_A);
    combine_kernel<<<dim3(N_TOK / 64, 2), 256, SMEM_COMBINE>>>(out);
}

// round 9
// speedup vs baseline: 1.6911x; 1.1213x over previous
#include <cuda_runtime.h>
#include <math.h>
#include <stdint.h>

// Problem constants (fixed shapes)
#define N_TOK 65536   // B*T
#define HDIM  512
#define NEXP  4
#define RNK   16
#define NC    4                    // n-chunks of 128 cols
#define NTILES (N_TOK / 128)       // 512 token tiles of 128

// ---------------- device scratch (static; no allocations) ----------------
__device__ float g_w[N_TOK * NEXP];                  // gate weights [N,4]
__device__ float g_wzp[NC * N_TOK * NEXP * RNK];     // partial z    [4][N][64]
__device__ float g_C[NEXP * RNK * HDIM];             // fused lora_B@fc2^T
__device__ float g_xr[N_TOK * HDIM];                 // tf32, col-permuted x
__device__ float g_wr[NEXP * HDIM * HDIM];           // tf32, col-permuted fc1_w

// ===================== helpers =====================
__device__ __forceinline__ uint32_t smem_to_u32(const void* p) {
    uint32_t a;
    asm("{ .reg .u64 t; cvta.to.shared.u64 t, %1; cvt.u32.u64 %0, t; }"
        : "=r"(a) : "l"(p));
    return a;
}
__device__ __forceinline__ void cp16(uint32_t dst, const float* src) {
    asm volatile("cp.async.cg.shared.global [%0], [%1], 16;" :: "r"(dst), "l"(src));
}
__device__ __forceinline__ uint32_t tf32_rna(float v) {
    uint32_t t;
    asm("cvt.rna.tf32.f32 %0, %1;" : "=r"(t) : "f"(v));
    return t;
}
__device__ __forceinline__ void mma_tf32(float c[4], const uint32_t a[4], const uint32_t b[2]) {
    asm volatile(
        "mma.sync.aligned.m16n8k8.row.col.f32.tf32.tf32.f32 "
        "{%0,%1,%2,%3}, {%4,%5,%6,%7}, {%8,%9}, {%0,%1,%2,%3};\n"
        : "+f"(c[0]), "+f"(c[1]), "+f"(c[2]), "+f"(c[3])
        : "r"(a[0]), "r"(a[1]), "r"(a[2]), "r"(a[3]), "r"(b[0]), "r"(b[1]));
}
__device__ __forceinline__ void fma2(uint64_t& d, uint64_t a, uint64_t b) {
    asm("fma.rn.f32x2 %0, %1, %2, %3;" : "=l"(d) : "l"(a), "l"(b), "l"(d));
}
__device__ __forceinline__ uint64_t pack2(float lo, float hi) {
    uint64_t r;
    asm("mov.b64 %0, {%1, %2};" : "=l"(r) : "r"(__float_as_uint(lo)), "r"(__float_as_uint(hi)));
    return r;
}

// =========================================================================
// Kernel 0a: fused x rounding (tf32, column-permuted) + gating.
//   One warp per token. Permutation in each 8-col group: c -> (c&3)*2+(c>>2).
// =========================================================================
__global__ void __launch_bounds__(256)
round_x_gating_kernel(const float* __restrict__ x,
                      const float* __restrict__ gate_w,
                      const float* __restrict__ thr_w) {
    const int warp = threadIdx.x >> 5, lane = threadIdx.x & 31;
    const int n = blockIdx.x * 8 + warp;
    const float* xr = x + (size_t)n * HDIM;
    float* xo = g_xr + (size_t)n * HDIM;

    float a0 = 0.f, a1 = 0.f, a2 = 0.f, a3 = 0.f, at = 0.f;
#pragma unroll
    for (int it = 0; it < 4; it++) {
        const int k0 = it * 128 + lane * 4;
        float4 v = *(const float4*)&xr[k0];
        float4 w0 = *(const float4*)&gate_w[0 * HDIM + k0];
        float4 w1 = *(const float4*)&gate_w[1 * HDIM + k0];
        float4 w2 = *(const float4*)&gate_w[2 * HDIM + k0];
        float4 w3 = *(const float4*)&gate_w[3 * HDIM + k0];
        float4 wt = *(const float4*)&thr_w[k0];
        a0 += v.x * w0.x + v.y * w0.y + v.z * w0.z + v.w * w0.w;
        a1 += v.x * w1.x + v.y * w1.y + v.z * w1.z + v.w * w1.w;
        a2 += v.x * w2.x + v.y * w2.y + v.z * w2.z + v.w * w2.w;
        a3 += v.x * w3.x + v.y * w3.y + v.z * w3.z + v.w * w3.w;
        at += v.x * wt.x + v.y * wt.y + v.z * wt.z + v.w * wt.w;
        const int base = k0 & ~7;
        const int odd = (k0 >> 2) & 1;
        ((uint32_t*)xo)[base + 0 + odd] = tf32_rna(v.x);
        ((uint32_t*)xo)[base + 2 + odd] = tf32_rna(v.y);
        ((uint32_t*)xo)[base + 4 + odd] = tf32_rna(v.z);
        ((uint32_t*)xo)[base + 6 + odd] = tf32_rna(v.w);
    }
#pragma unroll
    for (int off = 16; off > 0; off >>= 1) {
        a0 += __shfl_xor_sync(0xffffffffu, a0, off);
        a1 += __shfl_xor_sync(0xffffffffu, a1, off);
        a2 += __shfl_xor_sync(0xffffffffu, a2, off);
        a3 += __shfl_xor_sync(0xffffffffu, a3, off);
        at += __shfl_xor_sync(0xffffffffu, at, off);
    }
    if (lane == 0) {
        float m = fmaxf(fmaxf(a0, a1), fmaxf(a2, a3));
        float e0 = expf(a0 - m), e1 = expf(a1 - m), e2 = expf(a2 - m), e3 = expf(a3 - m);
        float inv_s = 1.f / (e0 + e1 + e2 + e3);
        float thr = (1.f / (1.f + expf(-at))) * 0.25f;
        float w0 = e0 * inv_s - thr, w1 = e1 * inv_s - thr;
        float w2 = e2 * inv_s - thr, w3 = e3 * inv_s - thr;
        w0 = (w0 >= 0.f) ? w0 : 0.f;  w1 = (w1 >= 0.f) ? w1 : 0.f;
        w2 = (w2 >= 0.f) ? w2 : 0.f;  w3 = (w3 >= 0.f) ? w3 : 0.f;
        float ws = w0 + w1 + w2 + w3;
        if (ws == 0.f) ws = 1.f;
        float inv = 1.f / ws;
        g_w[n * 4 + 0] = w0 * inv;  g_w[n * 4 + 1] = w1 * inv;
        g_w[n * 4 + 2] = w2 * inv;  g_w[n * 4 + 3] = w3 * inv;
    }
}

// =========================================================================
// Kernel 0b: round fc1_w to tf32, column-permuted.
// =========================================================================
__global__ void round_w_kernel(const float4* __restrict__ src) {
    int i = blockIdx.x * blockDim.x + threadIdx.x;   // float4 index
    float4 v = src[i];
    const int k = (i * 4) & (HDIM - 1);
    const size_t rowbase = (size_t)(i * 4 - k);
    const int base = k & ~7;
    const int odd = (k >> 2) & 1;
    uint32_t* dst = (uint32_t*)g_wr + rowbase;
    dst[base + 0 + odd] = tf32_rna(v.x);
    dst[base + 2 + odd] = tf32_rna(v.y);
    dst[base + 4 + odd] = tf32_rna(v.z);
    dst[base + 6 + odd] = tf32_rna(v.w);
}

// =========================================================================
// Kernel 1: C[e][r][d] = sum_o lora_B[e][r][o] * fc2_w[e][d][o]
// =========================================================================
__global__ void precompute_C_kernel(const float* __restrict__ lora_B,
                                    const float* __restrict__ fc2_w) {
    const int e = blockIdx.x;
    const int dbase = blockIdx.y * 64;
    __shared__ float lbs[RNK * HDIM];
    for (int i = threadIdx.x; i < RNK * HDIM; i += blockDim.x)
        lbs[i] = lora_B[(size_t)e * RNK * HDIM + i];
    __syncthreads();

    const int warp = threadIdx.x >> 5, lane = threadIdx.x & 31;
    for (int dd = 0; dd < 8; dd++) {
        const int d = dbase + warp * 8 + dd;
        float acc[RNK];
#pragma unroll
        for (int r = 0; r < RNK; r++) acc[r] = 0.f;
        const float* fr = fc2_w + ((size_t)e * HDIM + d) * HDIM;
        for (int o = lane; o < HDIM; o += 32) {
            float fv = fr[o];
#pragma unroll
            for (int r = 0; r < RNK; r++) acc[r] += fv * lbs[r * HDIM + o];
        }
#pragma unroll
        for (int r = 0; r < RNK; r++) {
#pragma unroll
            for (int off = 16; off > 0; off >>= 1)
                acc[r] += __shfl_xor_sync(0xffffffffu, acc[r], off);
        }
        if (lane == 0) {
#pragma unroll
            for (int r = 0; r < RNK; r++)
                g_C[(size_t)(e * RNK + r) * HDIM + d] = acc[r];
        }
    }
}

// =========================================================================
// Kernel 3: mma.sync tf32 expert kernel, 2 blocks/SM.
//   Block = (tile, nchunk, e): 128 tokens x 128 cols, K=512 in 16 chunks.
//   256 threads = 8 warps (2m x 4n), warp tile 64x32. 2-stage cp.async.
//   Epilogue: relu(H[128,128]) -> partial z -> g_wzp[nc] (raw z, no weight).
// =========================================================================
#define EX_STRIDE 40                        // words per smem row
#define EX_STAGE_B 20480                    // 128 rows * 160 B (each of A and B)
#define EX_A(s)   ((s) * 40960)
#define EX_B(s)   ((s) * 40960 + EX_STAGE_B)
#define EX_HS     0                         // [128][132] f32, aliases pipeline
#define EX_AST    81920                     // [16][132] f32
#define SMEM_EXP  (81920 + 16 * 132 * 4)    // 90368 B

__device__ __forceinline__ void ex_load_tile(uint32_t smem_base, int kt, int s, int n0,
                                             const float* __restrict__ Xe,
                                             const float* __restrict__ We, int tid) {
    const uint32_t abase = smem_base + EX_A(s);
    const uint32_t bbase = smem_base + EX_B(s);
    const int koff = kt * 32;
#pragma unroll
    for (int it = 0; it < 8; it++) {
        int idx = tid + it * 256;
        if (idx < 1024) {                 // A: 128 rows x 8 x 16B
            int row = idx >> 3, c = idx & 7;
            cp16(abase + row * 160 + c * 16, Xe + (size_t)row * HDIM + koff + c * 4);
        } else {                          // B: 128 rows x 8 x 16B
            int i = idx - 1024;
            int row = i >> 3, c = i & 7;
            cp16(bbase + row * 160 + c * 16,
                 We + (size_t)(n0 + row) * HDIM + koff + c * 4);
        }
    }
}

__global__ void __launch_bounds__(256, 2)
expert_mma_kernel(const float* __restrict__ lora_A) {
    const int tile = blockIdx.x;
    const int nc   = blockIdx.y;
    const int e    = blockIdx.z;
    const int m0   = tile * 128;
    const int n0   = nc * 128;
    const int tid  = threadIdx.x;
    const int warp = tid >> 5, lane = tid & 31;
    const int g = lane >> 2, tg = lane & 3;
    const int warp_m = warp >> 2, warp_n = warp & 3;   // 2 x 4

    extern __shared__ char smem[];
    const uint32_t smem_base = smem_to_u32(smem);
    float* Hs  = (float*)(smem + EX_HS);    // [128][132]
    float* Ast = (float*)(smem + EX_AST);   // [16][132]

    const float* Xe = g_xr + (size_t)m0 * HDIM;
    const float* We = g_wr + (size_t)e * HDIM * HDIM;
    const float* Ae = lora_A + (size_t)e * HDIM * RNK;

    // pipeline prologue
    ex_load_tile(smem_base, 0, 0, n0, Xe, We, tid);
    asm volatile("cp.async.commit_group;" ::: "memory");
    ex_load_tile(smem_base, 1, 1, n0, Xe, We, tid);
    asm volatile("cp.async.commit_group;" ::: "memory");

    float acc[4][4][4];
#pragma unroll
    for (int mi = 0; mi < 4; mi++)
#pragma unroll
        for (int ni = 0; ni < 4; ni++)
#pragma unroll
            for (int c = 0; c < 4; c++) acc[mi][ni][c] = 0.f;

    for (int kc = 0; kc < 16; kc++) {
        const int s = kc & 1;
        if (kc < 15) asm volatile("cp.async.wait_group 1;" ::: "memory");
        else         asm volatile("cp.async.wait_group 0;" ::: "memory");
        __syncthreads();

        const uint32_t* Xs = (const uint32_t*)(smem + EX_A(s));
        const uint32_t* Ws = (const uint32_t*)(smem + EX_B(s));
#pragma unroll
        for (int st = 0; st < 4; st++) {
            const int kk = st * 8;
            uint32_t a[4][4], b[4][2];
#pragma unroll
            for (int mi = 0; mi < 4; mi++) {
                const int row = warp_m * 64 + mi * 16 + g;
                uint2 lo = *(const uint2*)&Xs[row * EX_STRIDE + kk + 2 * tg];
                uint2 hi = *(const uint2*)&Xs[(row + 8) * EX_STRIDE + kk + 2 * tg];
                a[mi][0] = lo.x; a[mi][1] = hi.x; a[mi][2] = lo.y; a[mi][3] = hi.y;
            }
#pragma unroll
            for (int ni = 0; ni < 4; ni++) {
                const int col = warp_n * 32 + ni * 8 + g;
                uint2 bb = *(const uint2*)&Ws[col * EX_STRIDE + kk + 2 * tg];
                b[ni][0] = bb.x; b[ni][1] = bb.y;
            }
#pragma unroll
            for (int mi = 0; mi < 4; mi++)
#pragma unroll
                for (int ni = 0; ni < 4; ni++)
                    mma_tf32(acc[mi][ni], a[mi], b[ni]);
        }
        __syncthreads();   // stage s fully consumed -> safe to refill
        if (kc + 2 < 16) {
            ex_load_tile(smem_base, kc + 2, s, n0, Xe, We, tid);
            asm volatile("cp.async.commit_group;" ::: "memory");
        }
    }

    // stage lora_A chunk transposed: Ast[r][c] = A[n0+c][r]  (c in 0..127)
    for (int idx = tid; idx < 128 * RNK; idx += 256) {
        int r = idx >> 7, c = idx & 127;
        Ast[r * 132 + c] = Ae[(size_t)(n0 + c) * RNK + r];
    }
    __syncthreads();   // pipeline reads done (last barrier above) -> Hs aliases

    // relu(H) -> Hs
#pragma unroll
    for (int mi = 0; mi < 4; mi++)
#pragma unroll
        for (int ni = 0; ni < 4; ni++) {
            const int row = warp_m * 64 + mi * 16 + g;
            const int col = warp_n * 32 + ni * 8 + 2 * tg;
            Hs[row * 132 + col]           = fmaxf(acc[mi][ni][0], 0.f);
            Hs[row * 132 + col + 1]       = fmaxf(acc[mi][ni][1], 0.f);
            Hs[(row + 8) * 132 + col]     = fmaxf(acc[mi][ni][2], 0.f);
            Hs[(row + 8) * 132 + col + 1] = fmaxf(acc[mi][ni][3], 0.f);
        }
    __syncthreads();

    // partial z: thread (zr, zrowb) accumulates rows zrowb+16q, q=0..7
    const int zr = tid & 15;
    const int zrowb = tid >> 4;     // 0..15
    float zacc[8];
#pragma unroll
    for (int q = 0; q < 8; q++) zacc[q] = 0.f;
#pragma unroll
    for (int c4 = 0; c4 < 32; c4++) {
        float4 av = *(const float4*)&Ast[zr * 132 + c4 * 4];
#pragma unroll
        for (int q = 0; q < 8; q++) {
            float4 hv = *(const float4*)&Hs[(zrowb + 16 * q) * 132 + c4 * 4];
            zacc[q] += hv.x * av.x + hv.y * av.y + hv.z * av.z + hv.w * av.w;
        }
    }
#pragma unroll
    for (int q = 0; q < 8; q++) {
        const int n = m0 + zrowb + 16 * q;
        g_wzp[((size_t)nc * N_TOK + n) * (NEXP * RNK) + e * RNK + zr] = zacc[q];
    }
}

// =========================================================================
// Kernel 4: combine. out[n][dbase+d] = sum_j (sum_nc zp[nc][n][j]) * w[n][j>>4]
//                                           * C[j][dbase+d]
// Grid (1024 token-tiles, 2 d-halves); 2 blocks/SM; f32x2 inner loop.
// =========================================================================
#define SMEM_COMBINE ((64 * 256 + 64 * 68) * 4)

__global__ void __launch_bounds__(256, 2)
combine_kernel(float* __restrict__ out) {
    extern __shared__ float csmem[];
    float* Cs = csmem;               // [64][256]
    float* Zs = Cs + 64 * 256;       // [64][68]

    const int tile = blockIdx.x;
    const int dbase = blockIdx.y * 256;
    const int tid = threadIdx.x;

    for (int i = tid; i < 64 * 64; i += 256) {     // [64][256] as float4
        int j = i >> 6, c4 = i & 63;
        ((float4*)Cs)[i] = *(const float4*)&g_C[(size_t)j * HDIM + dbase + c4 * 4];
    }
    // Zs[row][j] = (sum_nc zp) * w   — 64 rows x 16 float4
    for (int i = tid; i < 64 * 16; i += 256) {
        int row = i >> 4, j4 = i & 15;
        const int n = tile * 64 + row;
        const size_t off = (size_t)n * 64 + j4 * 4;
        float4 s0 = *(const float4*)&g_wzp[0 * (size_t)N_TOK * 64 + off];
        float4 s1 = *(const float4*)&g_wzp[1 * (size_t)N_TOK * 64 + off];
        float4 s2 = *(const float4*)&g_wzp[2 * (size_t)N_TOK * 64 + off];
        float4 s3 = *(const float4*)&g_wzp[3 * (size_t)N_TOK * 64 + off];
        const float w = g_w[n * 4 + (j4 >> 2)];
        float4 r;
        r.x = (s0.x + s1.x + s2.x + s3.x) * w;
        r.y = (s0.y + s1.y + s2.y + s3.y) * w;
        r.z = (s0.z + s1.z + s2.z + s3.z) * w;
        r.w = (s0.w + s1.w + s2.w + s3.w) * w;
        *(float4*)&Zs[row * 68 + j4 * 4] = r;
    }
    __syncthreads();

    const int warp = tid >> 5, lane = tid & 31;
    const int rowbase = warp * 8;
    float* outt = out + (size_t)tile * 64 * HDIM + dbase;

    for (int rg = 0; rg < 2; rg++) {
        uint64_t acc[4][4];
#pragma unroll
        for (int rr = 0; rr < 4; rr++)
#pragma unroll
            for (int i = 0; i < 4; i++) acc[rr][i] = 0ull;

        for (int j = 0; j < 64; j++) {
            const uint64_t* c0 = (const uint64_t*)&Cs[j * 256 + lane * 4];
            const uint64_t* c1 = (const uint64_t*)&Cs[j * 256 + 128 + lane * 4];
            uint64_t p0 = c0[0], p1 = c0[1], p2 = c1[0], p3 = c1[1];
#pragma unroll
            for (int rr = 0; rr < 4; rr++) {
                const float zv = Zs[(rowbase + rg * 4 + rr) * 68 + j];
                uint64_t zz = pack2(zv, zv);
                fma2(acc[rr][0], zz, p0);
                fma2(acc[rr][1], zz, p1);
                fma2(acc[rr][2], zz, p2);
                fma2(acc[rr][3], zz, p3);
            }
        }
#pragma unroll
        for (int rr = 0; rr < 4; rr++) {
            const int row = rowbase + rg * 4 + rr;
            uint64_t* o0 = (uint64_t*)&outt[(size_t)row * HDIM + lane * 4];
            uint64_t* o1 = (uint64_t*)&outt[(size_t)row * HDIM + 128 + lane * 4];
            o0[0] = acc[rr][0];  o0[1] = acc[rr][1];
            o1[0] = acc[rr][2];  o1[1] = acc[rr][3];
        }
    }
}

// =========================================================================
extern "C" void kernel_launch(void* const* d_in, const int* in_sizes, int n_in,
                              void* d_out, int out_size) {
    const float* x      = (const float*)d_in[0];
    const float* gate_w = (const float*)d_in[1];
    const float* thr_w  = (const float*)d_in[2];
    const float* fc1_w  = (const float*)d_in[3];
    const float* lora_A = (const float*)d_in[4];
    const float* lora_B = (const float*)d_in[5];
    const float* fc2_w  = (const float*)d_in[6];
    float* out = (float*)d_out;

    cudaFuncSetAttribute(expert_mma_kernel,
                         cudaFuncAttributeMaxDynamicSharedMemorySize, SMEM_EXP);
    cudaFuncSetAttribute(combine_kernel,
                         cudaFuncAttributeMaxDynamicSharedMemorySize, SMEM_COMBINE);

    round_x_gating_kernel<<<N_TOK / 8, 256>>>(x, gate_w, thr_w);
    round_w_kernel<<<(NEXP * HDIM * HDIM / 4) / 256, 256>>>((const float4*)fc1_w);
    precompute_C_kernel<<<dim3(NEXP, HDIM / 64), 256>>>(lora_B, fc2_w);
    expert_mma_kernel<<<dim3(NTILES, NC, NEXP), 256, SMEM_EXP>>>(lora_A);
    combine_kernel<<<dim3(N_TOK / 64, 2), 256, SMEM_COMBINE>>>(out);
}

// round 12
// speedup vs baseline: 1.7387x; 1.0282x over previous
#include <cuda_runtime.h>
#include <math.h>
#include <stdint.h>

// Problem constants (fixed shapes)
#define N_TOK 65536   // B*T
#define HDIM  512
#define NEXP  4
#define RNK   16
#define NC    4                    // n-chunks of 128 cols
#define NTILES (N_TOK / 128)       // 512 token tiles of 128

// ---------------- device scratch (static; no allocations) ----------------
__device__ float g_w[N_TOK * NEXP];                  // gate weights [N,4]
__device__ float g_wzp[NC * N_TOK * NEXP * RNK];     // partial z    [4][N][64]
__device__ float g_C[NEXP * RNK * HDIM];             // fused lora_B@fc2^T
__device__ float g_xr[N_TOK * HDIM];                 // tf32, col-permuted x
__device__ float g_wr[NEXP * HDIM * HDIM];           // tf32, col-permuted fc1_w

// ===================== helpers =====================
__device__ __forceinline__ uint32_t smem_to_u32(const void* p) {
    uint32_t a;
    asm("{ .reg .u64 t; cvta.to.shared.u64 t, %1; cvt.u32.u64 %0, t; }"
        : "=r"(a) : "l"(p));
    return a;
}
__device__ __forceinline__ void cp16(uint32_t dst, const float* src) {
    asm volatile("cp.async.cg.shared.global [%0], [%1], 16;" :: "r"(dst), "l"(src));
}
__device__ __forceinline__ uint32_t tf32_rna(float v) {
    uint32_t t;
    asm("cvt.rna.tf32.f32 %0, %1;" : "=r"(t) : "f"(v));
    return t;
}
__device__ __forceinline__ void mma_tf32(float c[4], const uint32_t a[4], const uint32_t b[2]) {
    asm volatile(
        "mma.sync.aligned.m16n8k8.row.col.f32.tf32.tf32.f32 "
        "{%0,%1,%2,%3}, {%4,%5,%6,%7}, {%8,%9}, {%0,%1,%2,%3};\n"
        : "+f"(c[0]), "+f"(c[1]), "+f"(c[2]), "+f"(c[3])
        : "r"(a[0]), "r"(a[1]), "r"(a[2]), "r"(a[3]), "r"(b[0]), "r"(b[1]));
}
__device__ __forceinline__ void fma2(uint64_t& d, uint64_t a, uint64_t b) {
    asm("fma.rn.f32x2 %0, %1, %2, %3;" : "=l"(d) : "l"(a), "l"(b), "l"(d));
}
__device__ __forceinline__ uint64_t pack2(float lo, float hi) {
    uint64_t r;
    asm("mov.b64 %0, {%1, %2};" : "=l"(r) : "r"(__float_as_uint(lo)), "r"(__float_as_uint(hi)));
    return r;
}

// =========================================================================
// Kernel 0a: fused x rounding (tf32, column-permuted) + gating.
// =========================================================================
__global__ void __launch_bounds__(256)
round_x_gating_kernel(const float* __restrict__ x,
                      const float* __restrict__ gate_w,
                      const float* __restrict__ thr_w) {
    const int warp = threadIdx.x >> 5, lane = threadIdx.x & 31;
    const int n = blockIdx.x * 8 + warp;
    const float* xr = x + (size_t)n * HDIM;
    float* xo = g_xr + (size_t)n * HDIM;

    float a0 = 0.f, a1 = 0.f, a2 = 0.f, a3 = 0.f, at = 0.f;
#pragma unroll
    for (int it = 0; it < 4; it++) {
        const int k0 = it * 128 + lane * 4;
        float4 v = *(const float4*)&xr[k0];
        float4 w0 = *(const float4*)&gate_w[0 * HDIM + k0];
        float4 w1 = *(const float4*)&gate_w[1 * HDIM + k0];
        float4 w2 = *(const float4*)&gate_w[2 * HDIM + k0];
        float4 w3 = *(const float4*)&gate_w[3 * HDIM + k0];
        float4 wt = *(const float4*)&thr_w[k0];
        a0 += v.x * w0.x + v.y * w0.y + v.z * w0.z + v.w * w0.w;
        a1 += v.x * w1.x + v.y * w1.y + v.z * w1.z + v.w * w1.w;
        a2 += v.x * w2.x + v.y * w2.y + v.z * w2.z + v.w * w2.w;
        a3 += v.x * w3.x + v.y * w3.y + v.z * w3.z + v.w * w3.w;
        at += v.x * wt.x + v.y * wt.y + v.z * wt.z + v.w * wt.w;
        const int base = k0 & ~7;
        const int odd = (k0 >> 2) & 1;
        ((uint32_t*)xo)[base + 0 + odd] = tf32_rna(v.x);
        ((uint32_t*)xo)[base + 2 + odd] = tf32_rna(v.y);
        ((uint32_t*)xo)[base + 4 + odd] = tf32_rna(v.z);
        ((uint32_t*)xo)[base + 6 + odd] = tf32_rna(v.w);
    }
#pragma unroll
    for (int off = 16; off > 0; off >>= 1) {
        a0 += __shfl_xor_sync(0xffffffffu, a0, off);
        a1 += __shfl_xor_sync(0xffffffffu, a1, off);
        a2 += __shfl_xor_sync(0xffffffffu, a2, off);
        a3 += __shfl_xor_sync(0xffffffffu, a3, off);
        at += __shfl_xor_sync(0xffffffffu, at, off);
    }
    if (lane == 0) {
        float m = fmaxf(fmaxf(a0, a1), fmaxf(a2, a3));
        float e0 = expf(a0 - m), e1 = expf(a1 - m), e2 = expf(a2 - m), e3 = expf(a3 - m);
        float inv_s = 1.f / (e0 + e1 + e2 + e3);
        float thr = (1.f / (1.f + expf(-at))) * 0.25f;
        float w0 = e0 * inv_s - thr, w1 = e1 * inv_s - thr;
        float w2 = e2 * inv_s - thr, w3 = e3 * inv_s - thr;
        w0 = (w0 >= 0.f) ? w0 : 0.f;  w1 = (w1 >= 0.f) ? w1 : 0.f;
        w2 = (w2 >= 0.f) ? w2 : 0.f;  w3 = (w3 >= 0.f) ? w3 : 0.f;
        float ws = w0 + w1 + w2 + w3;
        if (ws == 0.f) ws = 1.f;
        float inv = 1.f / ws;
        g_w[n * 4 + 0] = w0 * inv;  g_w[n * 4 + 1] = w1 * inv;
        g_w[n * 4 + 2] = w2 * inv;  g_w[n * 4 + 3] = w3 * inv;
    }
}

// =========================================================================
// Kernel 0b: round fc1_w to tf32, column-permuted.
// =========================================================================
__global__ void round_w_kernel(const float4* __restrict__ src) {
    int i = blockIdx.x * blockDim.x + threadIdx.x;   // float4 index
    float4 v = src[i];
    const int k = (i * 4) & (HDIM - 1);
    const size_t rowbase = (size_t)(i * 4 - k);
    const int base = k & ~7;
    const int odd = (k >> 2) & 1;
    uint32_t* dst = (uint32_t*)g_wr + rowbase;
    dst[base + 0 + odd] = tf32_rna(v.x);
    dst[base + 2 + odd] = tf32_rna(v.y);
    dst[base + 4 + odd] = tf32_rna(v.z);
    dst[base + 6 + odd] = tf32_rna(v.w);
}

// =========================================================================
// Kernel 1: C[e][r][d] = sum_o lora_B[e][r][o] * fc2_w[e][d][o]
// =========================================================================
__global__ void precompute_C_kernel(const float* __restrict__ lora_B,
                                    const float* __restrict__ fc2_w) {
    const int e = blockIdx.x;
    const int dbase = blockIdx.y * 64;
    __shared__ float lbs[RNK * HDIM];
    for (int i = threadIdx.x; i < RNK * HDIM; i += blockDim.x)
        lbs[i] = lora_B[(size_t)e * RNK * HDIM + i];
    __syncthreads();

    const int warp = threadIdx.x >> 5, lane = threadIdx.x & 31;
    for (int dd = 0; dd < 8; dd++) {
        const int d = dbase + warp * 8 + dd;
        float acc[RNK];
#pragma unroll
        for (int r = 0; r < RNK; r++) acc[r] = 0.f;
        const float* fr = fc2_w + ((size_t)e * HDIM + d) * HDIM;
        for (int o = lane; o < HDIM; o += 32) {
            float fv = fr[o];
#pragma unroll
            for (int r = 0; r < RNK; r++) acc[r] += fv * lbs[r * HDIM + o];
        }
#pragma unroll
        for (int r = 0; r < RNK; r++) {
#pragma unroll
            for (int off = 16; off > 0; off >>= 1)
                acc[r] += __shfl_xor_sync(0xffffffffu, acc[r], off);
        }
        if (lane == 0) {
#pragma unroll
            for (int r = 0; r < RNK; r++)
                g_C[(size_t)(e * RNK + r) * HDIM + d] = acc[r];
        }
    }
}

// =========================================================================
// Kernel 3: mma.sync tf32 expert kernel, 2 blocks/SM.
//   Grid (16, NTILES): x = e*NC+nc (all 16 col-chunks of one token tile
//   co-resident -> X tile is L2-hit 16x, W fully L2-resident), y = tile.
//   Block: 128 tokens x 128 cols, K=512 in 16 chunks, 2-stage cp.async.
//   Per-thread global/smem offsets hoisted out of all loops.
// =========================================================================
#define EX_STRIDE 40                        // words per smem row
#define EX_STAGE_B 20480                    // 128 rows * 160 B (each of A and B)
#define EX_A(s)   ((s) * 40960)
#define EX_B(s)   ((s) * 40960 + EX_STAGE_B)
#define EX_HS     0                         // [128][132] f32, aliases pipeline
#define EX_AST    81920                     // [16][132] f32
#define SMEM_EXP  (81920 + 16 * 132 * 4)    // 90368 B

__global__ void __launch_bounds__(256, 2)
expert_mma_kernel(const float* __restrict__ lora_A) {
    const int e    = blockIdx.x >> 2;
    const int nc   = blockIdx.x & 3;
    const int tile = blockIdx.y;
    const int m0   = tile * 128;
    const int n0   = nc * 128;
    const int tid  = threadIdx.x;
    const int warp = tid >> 5, lane = tid & 31;
    const int g = lane >> 2, tg = lane & 3;
    const int warp_m = warp >> 2, warp_n = warp & 3;   // 2 x 4

    extern __shared__ char smem[];
    const uint32_t smem_base = smem_to_u32(smem);
    float* Hs  = (float*)(smem + EX_HS);    // [128][132]
    float* Ast = (float*)(smem + EX_AST);   // [16][132]

    const float* Xe = g_xr + (size_t)m0 * HDIM;
    const float* We = g_wr + (size_t)e * HDIM * HDIM + (size_t)n0 * HDIM;
    const float* Ae = lora_A + (size_t)e * HDIM * RNK;

    // ---- hoisted per-thread load roles (rows 0..127, granule c 0..7) ----
    const int lrow = tid >> 3, lc = tid & 7;                 // + it*32 rows
    const float* asrc = Xe + (size_t)lrow * HDIM + lc * 4;   // + koff
    const float* bsrc = We + (size_t)lrow * HDIM + lc * 4;
    const uint32_t sdst = smem_base + lrow * 160 + lc * 16;  // + stage offset

    // ---- hoisted fragment smem word-offsets ----
    const uint32_t xoff = (uint32_t)((warp_m * 64 + g) * EX_STRIDE + 2 * tg);
    const uint32_t woff = (uint32_t)((warp_n * 32 + g) * EX_STRIDE + 2 * tg);

#define EX_LOAD(kt, s) do {                                                  \
    const int _koff = (kt) * 32;                                             \
    const uint32_t _ab = sdst + EX_A(s);                                     \
    const uint32_t _bb = sdst + EX_B(s);                                     \
    _Pragma("unroll")                                                        \
    for (int _it = 0; _it < 4; _it++) {                                      \
        cp16(_ab + _it * (32 * 160), asrc + _koff + _it * (32 * HDIM));      \
        cp16(_bb + _it * (32 * 160), bsrc + _koff + _it * (32 * HDIM));      \
    }                                                                        \
    asm volatile("cp.async.commit_group;" ::: "memory");                     \
} while (0)

    EX_LOAD(0, 0);
    EX_LOAD(1, 1);

    float acc[4][4][4];
#pragma unroll
    for (int mi = 0; mi < 4; mi++)
#pragma unroll
        for (int ni = 0; ni < 4; ni++)
#pragma unroll
            for (int c = 0; c < 4; c++) acc[mi][ni][c] = 0.f;

    for (int kc = 0; kc < 16; kc++) {
        const int s = kc & 1;
        if (kc < 15) asm volatile("cp.async.wait_group 1;" ::: "memory");
        else         asm volatile("cp.async.wait_group 0;" ::: "memory");
        __syncthreads();

        const uint32_t* Xs = (const uint32_t*)(smem + EX_A(s)) + xoff;
        const uint32_t* Ws = (const uint32_t*)(smem + EX_B(s)) + woff;
#pragma unroll
        for (int st = 0; st < 4; st++) {
            const int kk = st * 8;
            uint32_t a[4][4], b[4][2];
#pragma unroll
            for (int mi = 0; mi < 4; mi++) {
                uint2 lo = *(const uint2*)&Xs[mi * (16 * EX_STRIDE) + kk];
                uint2 hi = *(const uint2*)&Xs[mi * (16 * EX_STRIDE) + 8 * EX_STRIDE + kk];
                a[mi][0] = lo.x; a[mi][1] = hi.x; a[mi][2] = lo.y; a[mi][3] = hi.y;
            }
#pragma unroll
            for (int ni = 0; ni < 4; ni++) {
                uint2 bb = *(const uint2*)&Ws[ni * (8 * EX_STRIDE) + kk];
                b[ni][0] = bb.x; b[ni][1] = bb.y;
            }
#pragma unroll
            for (int mi = 0; mi < 4; mi++)
#pragma unroll
                for (int ni = 0; ni < 4; ni++)
                    mma_tf32(acc[mi][ni], a[mi], b[ni]);
        }
        __syncthreads();   // stage s fully consumed -> safe to refill
        if (kc + 2 < 16) EX_LOAD(kc + 2, s);
    }

    // stage lora_A chunk transposed: Ast[r][c] = A[n0+c][r]  (c in 0..127)
    for (int idx = tid; idx < 128 * RNK; idx += 256) {
        int r = idx >> 7, c = idx & 127;
        Ast[r * 132 + c] = Ae[(size_t)(n0 + c) * RNK + r];
    }
    __syncthreads();   // pipeline reads done -> Hs aliases

    // relu(H) -> Hs
#pragma unroll
    for (int mi = 0; mi < 4; mi++)
#pragma unroll
        for (int ni = 0; ni < 4; ni++) {
            const int row = warp_m * 64 + mi * 16 + g;
            const int col = warp_n * 32 + ni * 8 + 2 * tg;
            Hs[row * 132 + col]           = fmaxf(acc[mi][ni][0], 0.f);
            Hs[row * 132 + col + 1]       = fmaxf(acc[mi][ni][1], 0.f);
            Hs[(row + 8) * 132 + col]     = fmaxf(acc[mi][ni][2], 0.f);
            Hs[(row + 8) * 132 + col + 1] = fmaxf(acc[mi][ni][3], 0.f);
        }
    __syncthreads();

    // partial z: thread (zr, zrowb) accumulates rows zrowb+16q, q=0..7
    const int zr = tid & 15;
    const int zrowb = tid >> 4;     // 0..15
    float zacc[8];
#pragma unroll
    for (int q = 0; q < 8; q++) zacc[q] = 0.f;
#pragma unroll
    for (int c4 = 0; c4 < 32; c4++) {
        float4 av = *(const float4*)&Ast[zr * 132 + c4 * 4];
#pragma unroll
        for (int q = 0; q < 8; q++) {
            float4 hv = *(const float4*)&Hs[(zrowb + 16 * q) * 132 + c4 * 4];
            zacc[q] += hv.x * av.x + hv.y * av.y + hv.z * av.z + hv.w * av.w;
        }
    }
#pragma unroll
    for (int q = 0; q < 8; q++) {
        const int n = m0 + zrowb + 16 * q;
        g_wzp[((size_t)nc * N_TOK + n) * (NEXP * RNK) + e * RNK + zr] = zacc[q];
    }
#undef EX_LOAD
}

// =========================================================================
// Kernel 4: combine. out[n][dbase+d] = sum_j (sum_nc zp[nc][n][j]) * w[n][j>>4]
//                                           * C[j][dbase+d]
// =========================================================================
#define SMEM_COMBINE ((64 * 256 + 64 * 68) * 4)

__global__ void __launch_bounds__(256, 2)
combine_kernel(float* __restrict__ out) {
    extern __shared__ float csmem[];
    float* Cs = csmem;               // [64][256]
    float* Zs = Cs + 64 * 256;       // [64][68]

    const int tile = blockIdx.x;
    const int dbase = blockIdx.y * 256;
    const int tid = threadIdx.x;

    for (int i = tid; i < 64 * 64; i += 256) {     // [64][256] as float4
        int j = i >> 6, c4 = i & 63;
        ((float4*)Cs)[i] = *(const float4*)&g_C[(size_t)j * HDIM + dbase + c4 * 4];
    }
    // Zs[row][j] = (sum_nc zp) * w
    for (int i = tid; i < 64 * 16; i += 256) {
        int row = i >> 4, j4 = i & 15;
        const int n = tile * 64 + row;
        const size_t off = (size_t)n * 64 + j4 * 4;
        float4 s0 = *(const float4*)&g_wzp[0 * (size_t)N_TOK * 64 + off];
        float4 s1 = *(const float4*)&g_wzp[1 * (size_t)N_TOK * 64 + off];
        float4 s2 = *(const float4*)&g_wzp[2 * (size_t)N_TOK * 64 + off];
        float4 s3 = *(const float4*)&g_wzp[3 * (size_t)N_TOK * 64 + off];
        const float w = g_w[n * 4 + (j4 >> 2)];
        float4 r;
        r.x = (s0.x + s1.x + s2.x + s3.x) * w;
        r.y = (s0.y + s1.y + s2.y + s3.y) * w;
        r.z = (s0.z + s1.z + s2.z + s3.z) * w;
        r.w = (s0.w + s1.w + s2.w + s3.w) * w;
        *(float4*)&Zs[row * 68 + j4 * 4] = r;
    }
    __syncthreads();

    const int warp = tid >> 5, lane = tid & 31;
    const int rowbase = warp * 8;
    float* outt = out + (size_t)tile * 64 * HDIM + dbase;

    for (int rg = 0; rg < 2; rg++) {
        uint64_t acc[4][4];
#pragma unroll
        for (int rr = 0; rr < 4; rr++)
#pragma unroll
            for (int i = 0; i < 4; i++) acc[rr][i] = 0ull;

        for (int j = 0; j < 64; j++) {
            const uint64_t* c0 = (const uint64_t*)&Cs[j * 256 + lane * 4];
            const uint64_t* c1 = (const uint64_t*)&Cs[j * 256 + 128 + lane * 4];
            uint64_t p0 = c0[0], p1 = c0[1], p2 = c1[0], p3 = c1[1];
#pragma unroll
            for (int rr = 0; rr < 4; rr++) {
                const float zv = Zs[(rowbase + rg * 4 + rr) * 68 + j];
                uint64_t zz = pack2(zv, zv);
                fma2(acc[rr][0], zz, p0);
                fma2(acc[rr][1], zz, p1);
                fma2(acc[rr][2], zz, p2);
                fma2(acc[rr][3], zz, p3);
            }
        }
#pragma unroll
        for (int rr = 0; rr < 4; rr++) {
            const int row = rowbase + rg * 4 + rr;
            uint64_t* o0 = (uint64_t*)&outt[(size_t)row * HDIM + lane * 4];
            uint64_t* o1 = (uint64_t*)&outt[(size_t)row * HDIM + 128 + lane * 4];
            o0[0] = acc[rr][0];  o0[1] = acc[rr][1];
            o1[0] = acc[rr][2];  o1[1] = acc[rr][3];
        }
    }
}

// =========================================================================
extern "C" void kernel_launch(void* const* d_in, const int* in_sizes, int n_in,
                              void* d_out, int out_size) {
    const float* x      = (const float*)d_in[0];
    const float* gate_w = (const float*)d_in[1];
    const float* thr_w  = (const float*)d_in[2];
    const float* fc1_w  = (const float*)d_in[3];
    const float* lora_A = (const float*)d_in[4];
    const float* lora_B = (const float*)d_in[5];
    const float* fc2_w  = (const float*)d_in[6];
    float* out = (float*)d_out;

    cudaFuncSetAttribute(expert_mma_kernel,
                         cudaFuncAttributeMaxDynamicSharedMemorySize, SMEM_EXP);
    cudaFuncSetAttribute(combine_kernel,
                         cudaFuncAttributeMaxDynamicSharedMemorySize, SMEM_COMBINE);

    round_x_gating_kernel<<<N_TOK / 8, 256>>>(x, gate_w, thr_w);
    round_w_kernel<<<(NEXP * HDIM * HDIM / 4) / 256, 256>>>((const float4*)fc1_w);
    precompute_C_kernel<<<dim3(NEXP, HDIM / 64), 256>>>(lora_B, fc2_w);
    expert_mma_kernel<<<dim3(NC * NEXP, NTILES), 256, SMEM_EXP>>>(lora_A);
    combine_kernel<<<dim3(N_TOK / 64, 2), 256, SMEM_COMBINE>>>(out);
}

// round 17
// speedup vs baseline: 1.7482x; 1.0055x over previous
#include <cuda_runtime.h>
#include <math.h>
#include <stdint.h>

// Problem constants (fixed shapes)
#define N_TOK 65536   // B*T
#define HDIM  512
#define NEXP  4
#define RNK   16
#define NC    4                    // n-chunks of 128 cols
#define NTILES (N_TOK / 128)       // 512 token tiles of 128

// ---------------- device scratch (static; no allocations) ----------------
__device__ float g_w[N_TOK * NEXP];                  // gate weights [N,4]
__device__ float g_wzp[NC * N_TOK * NEXP * RNK];     // partial z    [4][N][64]
__device__ float g_C[NEXP * RNK * HDIM];             // fused lora_B@fc2^T
__device__ float g_xr[N_TOK * HDIM];                 // tf32, 16-perm x
__device__ float g_wr[NEXP * HDIM * HDIM];           // tf32, 16-perm fc1_w

// ===================== helpers =====================
__device__ __forceinline__ uint32_t smem_to_u32(const void* p) {
    uint32_t a;
    asm("{ .reg .u64 t; cvta.to.shared.u64 t, %1; cvt.u32.u64 %0, t; }"
        : "=r"(a) : "l"(p));
    return a;
}
__device__ __forceinline__ void cp16(uint32_t dst, const float* src) {
    asm volatile("cp.async.cg.shared.global [%0], [%1], 16;" :: "r"(dst), "l"(src));
}
__device__ __forceinline__ uint32_t tf32_rna(float v) {
    uint32_t t;
    asm("cvt.rna.tf32.f32 %0, %1;" : "=r"(t) : "f"(v));
    return t;
}
__device__ __forceinline__ void mma_tf32(float c[4], uint32_t a0, uint32_t a1,
                                         uint32_t a2, uint32_t a3,
                                         uint32_t b0, uint32_t b1) {
    asm volatile(
        "mma.sync.aligned.m16n8k8.row.col.f32.tf32.tf32.f32 "
        "{%0,%1,%2,%3}, {%4,%5,%6,%7}, {%8,%9}, {%0,%1,%2,%3};\n"
        : "+f"(c[0]), "+f"(c[1]), "+f"(c[2]), "+f"(c[3])
        : "r"(a0), "r"(a1), "r"(a2), "r"(a3), "r"(b0), "r"(b1));
}
__device__ __forceinline__ void fma2(uint64_t& d, uint64_t a, uint64_t b) {
    asm("fma.rn.f32x2 %0, %1, %2, %3;" : "=l"(d) : "l"(a), "l"(b), "l"(d));
}
__device__ __forceinline__ uint64_t pack2(float lo, float hi) {
    uint64_t r;
    asm("mov.b64 %0, {%1, %2};" : "=l"(r) : "r"(__float_as_uint(lo)), "r"(__float_as_uint(hi)));
    return r;
}

// =========================================================================
// Kernel 0a: fused x rounding (tf32) + gating.
//   16-col-group permutation: c -> (c&3)*4 + (c>>2). For a float4 at
//   4-aligned k0: dst[base16 + ((k0>>2)&3) + 4*j] = v[j].
// =========================================================================
__global__ void __launch_bounds__(256)
round_x_gating_kernel(const float* __restrict__ x,
                      const float* __restrict__ gate_w,
                      const float* __restrict__ thr_w) {
    const int warp = threadIdx.x >> 5, lane = threadIdx.x & 31;
    const int n = blockIdx.x * 8 + warp;
    const float* xr = x + (size_t)n * HDIM;
    float* xo = g_xr + (size_t)n * HDIM;

    float a0 = 0.f, a1 = 0.f, a2 = 0.f, a3 = 0.f, at = 0.f;
#pragma unroll
    for (int it = 0; it < 4; it++) {
        const int k0 = it * 128 + lane * 4;
        float4 v = *(const float4*)&xr[k0];
        float4 w0 = *(const float4*)&gate_w[0 * HDIM + k0];
        float4 w1 = *(const float4*)&gate_w[1 * HDIM + k0];
        float4 w2 = *(const float4*)&gate_w[2 * HDIM + k0];
        float4 w3 = *(const float4*)&gate_w[3 * HDIM + k0];
        float4 wt = *(const float4*)&thr_w[k0];
        a0 += v.x * w0.x + v.y * w0.y + v.z * w0.z + v.w * w0.w;
        a1 += v.x * w1.x + v.y * w1.y + v.z * w1.z + v.w * w1.w;
        a2 += v.x * w2.x + v.y * w2.y + v.z * w2.z + v.w * w2.w;
        a3 += v.x * w3.x + v.y * w3.y + v.z * w3.z + v.w * w3.w;
        at += v.x * wt.x + v.y * wt.y + v.z * wt.z + v.w * wt.w;
        const int base16 = k0 & ~15;
        const int q = (k0 >> 2) & 3;
        ((uint32_t*)xo)[base16 + q + 0]  = tf32_rna(v.x);
        ((uint32_t*)xo)[base16 + q + 4]  = tf32_rna(v.y);
        ((uint32_t*)xo)[base16 + q + 8]  = tf32_rna(v.z);
        ((uint32_t*)xo)[base16 + q + 12] = tf32_rna(v.w);
    }
#pragma unroll
    for (int off = 16; off > 0; off >>= 1) {
        a0 += __shfl_xor_sync(0xffffffffu, a0, off);
        a1 += __shfl_xor_sync(0xffffffffu, a1, off);
        a2 += __shfl_xor_sync(0xffffffffu, a2, off);
        a3 += __shfl_xor_sync(0xffffffffu, a3, off);
        at += __shfl_xor_sync(0xffffffffu, at, off);
    }
    if (lane == 0) {
        float m = fmaxf(fmaxf(a0, a1), fmaxf(a2, a3));
        float e0 = expf(a0 - m), e1 = expf(a1 - m), e2 = expf(a2 - m), e3 = expf(a3 - m);
        float inv_s = 1.f / (e0 + e1 + e2 + e3);
        float thr = (1.f / (1.f + expf(-at))) * 0.25f;
        float w0 = e0 * inv_s - thr, w1 = e1 * inv_s - thr;
        float w2 = e2 * inv_s - thr, w3 = e3 * inv_s - thr;
        w0 = (w0 >= 0.f) ? w0 : 0.f;  w1 = (w1 >= 0.f) ? w1 : 0.f;
        w2 = (w2 >= 0.f) ? w2 : 0.f;  w3 = (w3 >= 0.f) ? w3 : 0.f;
        float ws = w0 + w1 + w2 + w3;
        if (ws == 0.f) ws = 1.f;
        float inv = 1.f / ws;
        g_w[n * 4 + 0] = w0 * inv;  g_w[n * 4 + 1] = w1 * inv;
        g_w[n * 4 + 2] = w2 * inv;  g_w[n * 4 + 3] = w3 * inv;
    }
}

// =========================================================================
// Kernel 0b: round fc1_w to tf32, 16-group-permuted.
// =========================================================================
__global__ void round_w_kernel(const float4* __restrict__ src) {
    int i = blockIdx.x * blockDim.x + threadIdx.x;   // float4 index
    float4 v = src[i];
    const int k = (i * 4) & (HDIM - 1);
    const size_t rowbase = (size_t)(i * 4 - k);
    const int base16 = k & ~15;
    const int q = (k >> 2) & 3;
    uint32_t* dst = (uint32_t*)g_wr + rowbase + base16 + q;
    dst[0]  = tf32_rna(v.x);
    dst[4]  = tf32_rna(v.y);
    dst[8]  = tf32_rna(v.z);
    dst[12] = tf32_rna(v.w);
}

// =========================================================================
// Kernel 1: C[e][r][d] = sum_o lora_B[e][r][o] * fc2_w[e][d][o]
// =========================================================================
__global__ void precompute_C_kernel(const float* __restrict__ lora_B,
                                    const float* __restrict__ fc2_w) {
    const int e = blockIdx.x;
    const int dbase = blockIdx.y * 64;
    __shared__ float lbs[RNK * HDIM];
    for (int i = threadIdx.x; i < RNK * HDIM; i += blockDim.x)
        lbs[i] = lora_B[(size_t)e * RNK * HDIM + i];
    __syncthreads();

    const int warp = threadIdx.x >> 5, lane = threadIdx.x & 31;
    for (int dd = 0; dd < 8; dd++) {
        const int d = dbase + warp * 8 + dd;
        float acc[RNK];
#pragma unroll
        for (int r = 0; r < RNK; r++) acc[r] = 0.f;
        const float* fr = fc2_w + ((size_t)e * HDIM + d) * HDIM;
        for (int o = lane; o < HDIM; o += 32) {
            float fv = fr[o];
#pragma unroll
            for (int r = 0; r < RNK; r++) acc[r] += fv * lbs[r * HDIM + o];
        }
#pragma unroll
        for (int r = 0; r < RNK; r++) {
#pragma unroll
            for (int off = 16; off > 0; off >>= 1)
                acc[r] += __shfl_xor_sync(0xffffffffu, acc[r], off);
        }
        if (lane == 0) {
#pragma unroll
            for (int r = 0; r < RNK; r++)
                g_C[(size_t)(e * RNK + r) * HDIM + d] = acc[r];
        }
    }
}

// =========================================================================
// Kernel 3: mma.sync tf32 expert kernel, 2 blocks/SM.
//   Grid (16, NTILES): x = e*NC+nc, y = tile (X tile L2-hit 16x).
//   Block: 128 tokens x 128 cols, K=512 in 16 chunks, 2-stage cp.async.
//   Fragments via LDS.128: one uint4 covers 2 k-steps (16-group perm).
//   Row stride 48 words -> conflict-free .128 phases.
// =========================================================================
#define EX_STRIDE 48                        // words per smem row (192 B)
#define EX_STAGE  49152                     // 256 rows * 192 B
#define EX_A(s)   ((s) * EX_STAGE)
#define EX_B(s)   ((s) * EX_STAGE + 24576)
#define EX_HS     0                         // [128][132] f32, aliases pipeline
#define EX_AST    98304                     // [16][132] f32
#define SMEM_EXP  (98304 + 16 * 132 * 4)    // 106752 B (x2 = 213.5 KB/SM)

__global__ void __launch_bounds__(256, 2)
expert_mma_kernel(const float* __restrict__ lora_A) {
    const int e    = blockIdx.x >> 2;
    const int nc   = blockIdx.x & 3;
    const int tile = blockIdx.y;
    const int m0   = tile * 128;
    const int n0   = nc * 128;
    const int tid  = threadIdx.x;
    const int warp = tid >> 5, lane = tid & 31;
    const int g = lane >> 2, tg = lane & 3;
    const int warp_m = warp >> 2, warp_n = warp & 3;   // 2 x 4

    extern __shared__ char smem[];
    const uint32_t smem_base = smem_to_u32(smem);
    float* Hs  = (float*)(smem + EX_HS);    // [128][132]
    float* Ast = (float*)(smem + EX_AST);   // [16][132]

    const float* Xe = g_xr + (size_t)m0 * HDIM;
    const float* We = g_wr + (size_t)e * HDIM * HDIM + (size_t)n0 * HDIM;
    const float* Ae = lora_A + (size_t)e * HDIM * RNK;

    // ---- hoisted per-thread load roles (row 0..31 +it*32, granule lc) ----
    const int lrow = tid >> 3, lc = tid & 7;
    const float* asrc = Xe + (size_t)lrow * HDIM + lc * 4;
    const float* bsrc = We + (size_t)lrow * HDIM + lc * 4;
    const uint32_t sdst = smem_base + lrow * 192 + lc * 16;

    // ---- hoisted fragment word-offsets (add sp*16 per k-step-pair) ----
    const uint32_t xoff = (uint32_t)((warp_m * 64 + g) * EX_STRIDE + tg * 4);
    const uint32_t woff = (uint32_t)((warp_n * 32 + g) * EX_STRIDE + tg * 4);

#define EX_LOAD(kt, s) do {                                                  \
    const int _koff = (kt) * 32;                                             \
    const uint32_t _ab = sdst + EX_A(s);                                     \
    const uint32_t _bb = sdst + EX_B(s);                                     \
    _Pragma("unroll")                                                        \
    for (int _it = 0; _it < 4; _it++) {                                      \
        cp16(_ab + _it * (32 * 192), asrc + _koff + _it * (32 * HDIM));      \
        cp16(_bb + _it * (32 * 192), bsrc + _koff + _it * (32 * HDIM));      \
    }                                                                        \
    asm volatile("cp.async.commit_group;" ::: "memory");                     \
} while (0)

    EX_LOAD(0, 0);
    EX_LOAD(1, 1);

    float acc[4][4][4];
#pragma unroll
    for (int mi = 0; mi < 4; mi++)
#pragma unroll
        for (int ni = 0; ni < 4; ni++)
#pragma unroll
            for (int c = 0; c < 4; c++) acc[mi][ni][c] = 0.f;

    for (int kc = 0; kc < 16; kc++) {
        const int s = kc & 1;
        if (kc < 15) asm volatile("cp.async.wait_group 1;" ::: "memory");
        else         asm volatile("cp.async.wait_group 0;" ::: "memory");
        __syncthreads();

        const uint32_t* Xs = (const uint32_t*)(smem + EX_A(s)) + xoff;
        const uint32_t* Ws = (const uint32_t*)(smem + EX_B(s)) + woff;
#pragma unroll
        for (int sp = 0; sp < 2; sp++) {         // k-step pairs (k 0..15 / 16..31)
            const int ko = sp * 16;
            uint4 bq[4];
#pragma unroll
            for (int ni = 0; ni < 4; ni++)
                bq[ni] = *(const uint4*)&Ws[ni * (8 * EX_STRIDE) + ko];
#pragma unroll
            for (int mp = 0; mp < 2; mp++) {     // mi pairs: limit live regs
                uint4 aq[2][2];
#pragma unroll
                for (int m2 = 0; m2 < 2; m2++) {
                    const int mi = mp * 2 + m2;
                    aq[m2][0] = *(const uint4*)&Xs[mi * (16 * EX_STRIDE) + ko];
                    aq[m2][1] = *(const uint4*)&Xs[mi * (16 * EX_STRIDE) + 8 * EX_STRIDE + ko];
                }
#pragma unroll
                for (int m2 = 0; m2 < 2; m2++) {
                    const int mi = mp * 2 + m2;
#pragma unroll
                    for (int ni = 0; ni < 4; ni++) {
                        mma_tf32(acc[mi][ni], aq[m2][0].x, aq[m2][1].x,
                                 aq[m2][0].y, aq[m2][1].y, bq[ni].x, bq[ni].y);
                        mma_tf32(acc[mi][ni], aq[m2][0].z, aq[m2][1].z,
                                 aq[m2][0].w, aq[m2][1].w, bq[ni].z, bq[ni].w);
                    }
                }
            }
        }
        __syncthreads();   // stage s fully consumed -> safe to refill
        if (kc + 2 < 16) EX_LOAD(kc + 2, s);
    }

    // stage lora_A chunk transposed: Ast[r][c] = A[n0+c][r]  (c in 0..127)
    for (int idx = tid; idx < 128 * RNK; idx += 256) {
        int r = idx >> 7, c = idx & 127;
        Ast[r * 132 + c] = Ae[(size_t)(n0 + c) * RNK + r];
    }
    __syncthreads();   // pipeline reads done -> Hs aliases

    // relu(H) -> Hs
#pragma unroll
    for (int mi = 0; mi < 4; mi++)
#pragma unroll
        for (int ni = 0; ni < 4; ni++) {
            const int row = warp_m * 64 + mi * 16 + g;
            const int col = warp_n * 32 + ni * 8 + 2 * tg;
            Hs[row * 132 + col]           = fmaxf(acc[mi][ni][0], 0.f);
            Hs[row * 132 + col + 1]       = fmaxf(acc[mi][ni][1], 0.f);
            Hs[(row + 8) * 132 + col]     = fmaxf(acc[mi][ni][2], 0.f);
            Hs[(row + 8) * 132 + col + 1] = fmaxf(acc[mi][ni][3], 0.f);
        }
    __syncthreads();

    // partial z: thread (zr, zrowb) accumulates rows zrowb+16q, q=0..7
    const int zr = tid & 15;
    const int zrowb = tid >> 4;     // 0..15
    float zacc[8];
#pragma unroll
    for (int q = 0; q < 8; q++) zacc[q] = 0.f;
#pragma unroll
    for (int c4 = 0; c4 < 32; c4++) {
        float4 av = *(const float4*)&Ast[zr * 132 + c4 * 4];
#pragma unroll
        for (int q = 0; q < 8; q++) {
            float4 hv = *(const float4*)&Hs[(zrowb + 16 * q) * 132 + c4 * 4];
            zacc[q] += hv.x * av.x + hv.y * av.y + hv.z * av.z + hv.w * av.w;
        }
    }
#pragma unroll
    for (int q = 0; q < 8; q++) {
        const int n = m0 + zrowb + 16 * q;
        g_wzp[((size_t)nc * N_TOK + n) * (NEXP * RNK) + e * RNK + zr] = zacc[q];
    }
#undef EX_LOAD
}

// =========================================================================
// Kernel 4: combine. out[n][dbase+d] = sum_j (sum_nc zp[nc][n][j]) * w[n][j>>4]
//                                           * C[j][dbase+d]
// =========================================================================
#define SMEM_COMBINE ((64 * 256 + 64 * 68) * 4)

__global__ void __launch_bounds__(256, 2)
combine_kernel(float* __restrict__ out) {
    extern __shared__ float csmem[];
    float* Cs = csmem;               // [64][256]
    float* Zs = Cs + 64 * 256;       // [64][68]

    const int tile = blockIdx.x;
    const int dbase = blockIdx.y * 256;
    const int tid = threadIdx.x;

    for (int i = tid; i < 64 * 64; i += 256) {     // [64][256] as float4
        int j = i >> 6, c4 = i & 63;
        ((float4*)Cs)[i] = *(const float4*)&g_C[(size_t)j * HDIM + dbase + c4 * 4];
    }
    // Zs[row][j] = (sum_nc zp) * w
    for (int i = tid; i < 64 * 16; i += 256) {
        int row = i >> 4, j4 = i & 15;
        const int n = tile * 64 + row;
        const size_t off = (size_t)n * 64 + j4 * 4;
        float4 s0 = *(const float4*)&g_wzp[0 * (size_t)N_TOK * 64 + off];
        float4 s1 = *(const float4*)&g_wzp[1 * (size_t)N_TOK * 64 + off];
        float4 s2 = *(const float4*)&g_wzp[2 * (size_t)N_TOK * 64 + off];
        float4 s3 = *(const float4*)&g_wzp[3 * (size_t)N_TOK * 64 + off];
        const float w = g_w[n * 4 + (j4 >> 2)];
        float4 r;
        r.x = (s0.x + s1.x + s2.x + s3.x) * w;
        r.y = (s0.y + s1.y + s2.y + s3.y) * w;
        r.z = (s0.z + s1.z + s2.z + s3.z) * w;
        r.w = (s0.w + s1.w + s2.w + s3.w) * w;
        *(float4*)&Zs[row * 68 + j4 * 4] = r;
    }
    __syncthreads();

    const int warp = tid >> 5, lane = tid & 31;
    const int rowbase = warp * 8;
    float* outt = out + (size_t)tile * 64 * HDIM + dbase;

    for (int rg = 0; rg < 2; rg++) {
        uint64_t acc[4][4];
#pragma unroll
        for (int rr = 0; rr < 4; rr++)
#pragma unroll
            for (int i = 0; i < 4; i++) acc[rr][i] = 0ull;

        for (int j = 0; j < 64; j++) {
            const uint64_t* c0 = (const uint64_t*)&Cs[j * 256 + lane * 4];
            const uint64_t* c1 = (const uint64_t*)&Cs[j * 256 + 128 + lane * 4];
            uint64_t p0 = c0[0], p1 = c0[1], p2 = c1[0], p3 = c1[1];
#pragma unroll
            for (int rr = 0; rr < 4; rr++) {
                const float zv = Zs[(rowbase + rg * 4 + rr) * 68 + j];
                uint64_t zz = pack2(zv, zv);
                fma2(acc[rr][0], zz, p0);
                fma2(acc[rr][1], zz, p1);
                fma2(acc[rr][2], zz, p2);
                fma2(acc[rr][3], zz, p3);
            }
        }
#pragma unroll
        for (int rr = 0; rr < 4; rr++) {
            const int row = rowbase + rg * 4 + rr;
            uint64_t* o0 = (uint64_t*)&outt[(size_t)row * HDIM + lane * 4];
            uint64_t* o1 = (uint64_t*)&outt[(size_t)row * HDIM + 128 + lane * 4];
            o0[0] = acc[rr][0];  o0[1] = acc[rr][1];
            o1[0] = acc[rr][2];  o1[1] = acc[rr][3];
        }
    }
}

// =========================================================================
extern "C" void kernel_launch(void* const* d_in, const int* in_sizes, int n_in,
                              void* d_out, int out_size) {
    const float* x      = (const float*)d_in[0];
    const float* gate_w = (const float*)d_in[1];
    const float* thr_w  = (const float*)d_in[2];
    const float* fc1_w  = (const float*)d_in[3];
    const float* lora_A = (const float*)d_in[4];
    const float* lora_B = (const float*)d_in[5];
    const float* fc2_w  = (const float*)d_in[6];
    float* out = (float*)d_out;

    cudaFuncSetAttribute(expert_mma_kernel,
                         cudaFuncAttributeMaxDynamicSharedMemorySize, SMEM_EXP);
    cudaFuncSetAttribute(combine_kernel,
                         cudaFuncAttributeMaxDynamicSharedMemorySize, SMEM_COMBINE);

    round_x_gating_kernel<<<N_TOK / 8, 256>>>(x, gate_w, thr_w);
    round_w_kernel<<<(NEXP * HDIM * HDIM / 4) / 256, 256>>>((const float4*)fc1_w);
    precompute_C_kernel<<<dim3(NEXP, HDIM / 64), 256>>>(lora_B, fc2_w);
    expert_mma_kernel<<<dim3(NC * NEXP, NTILES), 256, SMEM_EXP>>>(lora_A);
    combine_kernel<<<dim3(N_TOK / 64, 2), 256, SMEM_COMBINE>>>(out);
}